// round 11
// baseline (speedup 1.0000x reference)
#include <cuda_runtime.h>
#include <cuda_fp16.h>
#include <math.h>
#include <stdint.h>

#define NN   100000
#define NE   1600000
#define DIM  256
#define DOUT 40

// ---------------- scratch (static device globals; no runtime alloc) ----------
__device__ int    g_deg[NN];
__device__ int    g_cursor[NN];
__device__ int    g_rowptr[NN + 1];
__device__ int    g_col[NE];
__device__ int    g_bsum[256];
__device__ float  g_invdeg[NN];
__device__ __half g_xh[(size_t)NN * DIM];
__device__ __half g_meanh[(size_t)NN * DIM];
__device__ __half g_h0h[(size_t)NN * DIM];
__device__ __half g_h1h[(size_t)NN * DIM];
__device__ __half g_zh[(size_t)NN * 80];       // layer-2 projected [yl(40)|yr(40)] fp16
__device__ __half g_Wl0h[DIM * DIM];           // transposed [n][k] fp16
__device__ __half g_Wr0h[DIM * DIM];
__device__ __half g_Wl1h[DIM * DIM];
__device__ __half g_Wr1h[DIM * DIM];
__device__ __half g_W2h[80 * DIM];             // [n(80)][k(256)]

// ---------------- fused prep: conv_x + zero_deg + all weight packs -----------
#define PREP_TOTAL 6782624
__global__ void prep_k(const float* __restrict__ x,
                       const float* __restrict__ Wl0, const float* __restrict__ Wr0,
                       const float* __restrict__ Wl1, const float* __restrict__ Wr1,
                       const float* __restrict__ Wl2, const float* __restrict__ Wr2) {
    int i = blockIdx.x * blockDim.x + threadIdx.x;
    if (i < 6400000) {
        float4 v = *reinterpret_cast<const float4*>(x + (size_t)i * 4);
        __half2 h0 = __floats2half2_rn(v.x, v.y);
        __half2 h1 = __floats2half2_rn(v.z, v.w);
        uint2 pk;
        pk.x = *reinterpret_cast<unsigned*>(&h0);
        pk.y = *reinterpret_cast<unsigned*>(&h1);
        *reinterpret_cast<uint2*>(g_xh + (size_t)i * 4) = pk;
    } else if (i < 6500000) {
        g_deg[i - 6400000] = 0;
    } else if (i < 6762144) {
        int j = i - 6500000;
        int w = j >> 16;
        int r = j & 65535;
        const float* W = (w == 0) ? Wl0 : (w == 1) ? Wr0 : (w == 2) ? Wl1 : Wr1;
        __half* o = (w == 0) ? g_Wl0h : (w == 1) ? g_Wr0h : (w == 2) ? g_Wl1h : g_Wr1h;
        int n = r >> 8, k = r & 255;
        o[(size_t)n * DIM + k] = __float2half_rn(W[(size_t)k * DIM + n]);
    } else if (i < PREP_TOTAL) {
        int j = i - 6762144;
        int w = j / 10240, r = j % 10240;
        const float* W = w ? Wr2 : Wl2;
        int n = r >> 8, k = r & 255;
        g_W2h[(size_t)(w * 40 + n) * DIM + k] = __float2half_rn(W[(size_t)k * DOUT + n]);
    }
}

// ---------------- CSR build --------------------------------------------------
__global__ void count_deg_k(const int* __restrict__ dst) {
    int e = blockIdx.x * blockDim.x + threadIdx.x;
    if (e < NE) atomicAdd(&g_deg[dst[e]], 1);
}

#define NB1 196   // ceil(NN / 512)
__global__ void scan1_k() {
    __shared__ int wsum[16];
    int tid = threadIdx.x, lane = tid & 31, wid = tid >> 5;
    int i = blockIdx.x * 512 + tid;
    int v = (i < NN) ? g_deg[i] : 0;
    int x = v;
    #pragma unroll
    for (int off = 1; off < 32; off <<= 1) {
        int t = __shfl_up_sync(0xffffffffu, x, off);
        if (lane >= off) x += t;
    }
    if (lane == 31) wsum[wid] = x;
    __syncthreads();
    if (wid == 0 && lane < 16) {
        int w = wsum[lane];
        #pragma unroll
        for (int off = 1; off < 16; off <<= 1) {
            int t = __shfl_up_sync(0x0000ffffu, w, off);
            if (lane >= off) w += t;
        }
        wsum[lane] = w;
    }
    __syncthreads();
    int excl = x - v + ((wid > 0) ? wsum[wid - 1] : 0);
    if (i < NN) g_rowptr[i] = excl;
    if (tid == 0) g_bsum[blockIdx.x] = wsum[15];
}

__global__ void scan2_k() {
    __shared__ int sm[256];
    int t = threadIdx.x;
    int v = (t < NB1) ? g_bsum[t] : 0;
    sm[t] = v;
    __syncthreads();
    #pragma unroll
    for (int off = 1; off < 256; off <<= 1) {
        int add = (t >= off) ? sm[t - off] : 0;
        __syncthreads();
        sm[t] += add;
        __syncthreads();
    }
    if (t < NB1) g_bsum[t] = sm[t] - v;
    if (t == NB1 - 1) g_rowptr[NN] = sm[t];
}

__global__ void scan3_k() {
    int i = blockIdx.x * blockDim.x + threadIdx.x;
    if (i < NN) {
        int e = g_rowptr[i] + g_bsum[i >> 9];
        g_rowptr[i] = e;
        g_cursor[i] = e;
        int d = g_deg[i];
        g_invdeg[i] = 1.0f / (float)((d > 1) ? d : 1);
    }
}

__global__ void fill_csr_k(const int* __restrict__ src, const int* __restrict__ dst) {
    int e = blockIdx.x * blockDim.x + threadIdx.x;
    if (e < NE) {
        int d = dst[e];
        int p = atomicAdd(&g_cursor[d], 1);
        g_col[p] = src[e];
    }
}

// ---------------- aggregation (fp16 gather, fp32 accumulate) -----------------
__device__ __forceinline__ void acc8(float* s, uint4 v) {
    __half2 a = *reinterpret_cast<__half2*>(&v.x);
    __half2 b = *reinterpret_cast<__half2*>(&v.y);
    __half2 c = *reinterpret_cast<__half2*>(&v.z);
    __half2 d = *reinterpret_cast<__half2*>(&v.w);
    float2 fa = __half22float2(a), fb = __half22float2(b);
    float2 fc = __half22float2(c), fd = __half22float2(d);
    s[0] += fa.x; s[1] += fa.y; s[2] += fb.x; s[3] += fb.y;
    s[4] += fc.x; s[5] += fc.y; s[6] += fd.x; s[7] += fd.y;
}

__global__ void aggregate_h_k(const __half* __restrict__ h) {
    int node = (int)((blockIdx.x * blockDim.x + threadIdx.x) >> 5);
    if (node >= NN) return;
    int lane = threadIdx.x & 31;
    int beg = g_rowptr[node], end = g_rowptr[node + 1];
    float s[8];
    #pragma unroll
    for (int q = 0; q < 8; ++q) s[q] = 0.f;
    int e = beg;
    for (; e + 3 < end; e += 4) {
        int i0 = g_col[e], i1 = g_col[e + 1], i2 = g_col[e + 2], i3 = g_col[e + 3];
        uint4 v0 = __ldg(reinterpret_cast<const uint4*>(h + (size_t)i0 * DIM) + lane);
        uint4 v1 = __ldg(reinterpret_cast<const uint4*>(h + (size_t)i1 * DIM) + lane);
        uint4 v2 = __ldg(reinterpret_cast<const uint4*>(h + (size_t)i2 * DIM) + lane);
        uint4 v3 = __ldg(reinterpret_cast<const uint4*>(h + (size_t)i3 * DIM) + lane);
        acc8(s, v0); acc8(s, v1); acc8(s, v2); acc8(s, v3);
    }
    for (; e < end; ++e) {
        int i0 = g_col[e];
        uint4 v0 = __ldg(reinterpret_cast<const uint4*>(h + (size_t)i0 * DIM) + lane);
        acc8(s, v0);
    }
    float inv = g_invdeg[node];
    __half2 o0 = __floats2half2_rn(s[0] * inv, s[1] * inv);
    __half2 o1 = __floats2half2_rn(s[2] * inv, s[3] * inv);
    __half2 o2 = __floats2half2_rn(s[4] * inv, s[5] * inv);
    __half2 o3 = __floats2half2_rn(s[6] * inv, s[7] * inv);
    uint4 pk;
    pk.x = *reinterpret_cast<unsigned*>(&o0);
    pk.y = *reinterpret_cast<unsigned*>(&o1);
    pk.z = *reinterpret_cast<unsigned*>(&o2);
    pk.w = *reinterpret_cast<unsigned*>(&o3);
    *(reinterpret_cast<uint4*>(g_meanh + (size_t)node * DIM) + lane) = pk;
}

// ---------------- fp16 tensor-core GEMM (cp.async 4-stage + ldmatrix) --------
__device__ __forceinline__ uint32_t smem_u32(const void* p) {
    uint32_t a;
    asm("{ .reg .u64 t; cvta.to.shared.u64 t, %1; cvt.u32.u64 %0, t; }"
        : "=r"(a) : "l"(p));
    return a;
}

__device__ __forceinline__ void mma_f16(float* d, const unsigned* a, const unsigned* b) {
    asm volatile(
        "mma.sync.aligned.m16n8k16.row.col.f32.f16.f16.f32 "
        "{%0,%1,%2,%3}, {%4,%5,%6,%7}, {%8,%9}, {%0,%1,%2,%3};"
        : "+f"(d[0]), "+f"(d[1]), "+f"(d[2]), "+f"(d[3])
        : "r"(a[0]), "r"(a[1]), "r"(a[2]), "r"(a[3]),
          "r"(b[0]), "r"(b[1]));
}

__device__ __forceinline__ void ldsm_x4(unsigned& r0, unsigned& r1,
                                        unsigned& r2, unsigned& r3, uint32_t addr) {
    asm volatile("ldmatrix.sync.aligned.m8n8.x4.shared.b16 {%0,%1,%2,%3}, [%4];"
                 : "=r"(r0), "=r"(r1), "=r"(r2), "=r"(r3) : "r"(addr));
}

#define CP_A16(dst, src) \
    asm volatile("cp.async.cg.shared.global [%0], [%1], 16;" \
                 :: "r"(dst), "l"(src) : "memory")
#define CP_COMMIT() asm volatile("cp.async.commit_group;" ::: "memory")
#define CP_WAIT2()  asm volatile("cp.async.wait_group 2;" ::: "memory")

// C = A0@W0^T (+ A1@W1^T) + bias; A fp16 [row][k] stride DIM, W fp16 [n][k] stride DIM.
// BM=128 BN=128, K flattened into NT=nphase*16 k16-tiles, 4-stage cp.async ring.
#define SA 24
#define GSTAGE_B (128 * SA * 2)            // 6144 B per matrix per stage
#define GSMEM_TOTAL (8 * GSTAGE_B)         // 4 stages x (A + W) = 49152 B
template<bool RELU, bool HALF_OUT>
__global__ __launch_bounds__(256) void gemm_f16_k(
    const __half* __restrict__ A0, const __half* __restrict__ A1,
    const __half* __restrict__ W0, const __half* __restrict__ W1,
    const float* __restrict__ bias,
    __half* __restrict__ Ch, float* __restrict__ Cf,
    int Nout, int nphase)
{
    extern __shared__ __align__(16) __half smem_[];
    int tid = threadIdx.x;
    int lane = tid & 31, wid = tid >> 5;
    int wr = wid >> 1, wc = wid & 1;
    int i0 = blockIdx.x * 128, j0 = blockIdx.y * 128;
    const int NT = nphase * 16;

    // load coords: each thread = one 16B chunk of A and one of W per tile
    int arow = tid >> 1, akb = (tid & 1) << 3;
    int gi = i0 + arow; if (gi >= NN) gi = NN - 1;
    int wrow = j0 + arow; if (wrow >= Nout) wrow = Nout - 1;

    const uint32_t a_sm0 = smem_u32(smem_);
    const uint32_t w_sm0 = a_sm0 + 4 * GSTAGE_B;
    const uint32_t dst_off = (uint32_t)(arow * SA + akb) * 2;

    float acc[2][8][4];
    #pragma unroll
    for (int mi = 0; mi < 2; ++mi)
        #pragma unroll
        for (int ni = 0; ni < 8; ++ni)
            #pragma unroll
            for (int q = 0; q < 4; ++q) acc[mi][ni][q] = 0.f;

    const int lrow = lane & 15;
    const int lcol = (lane >> 4) << 3;
    const int r4 = lane >> 2, c4 = lane & 3;

    #define GLOAD(T, BUF) do {                                                \
        int _ph = (T) >> 4, _k0 = ((T) & 15) << 4;                            \
        const __half* _Ap = _ph ? A1 : A0;                                    \
        const __half* _Wp = _ph ? W1 : W0;                                    \
        CP_A16(a_sm0 + (BUF) * GSTAGE_B + dst_off,                            \
               _Ap + (size_t)gi * DIM + _k0 + akb);                           \
        CP_A16(w_sm0 + (BUF) * GSTAGE_B + dst_off,                            \
               _Wp + (size_t)wrow * DIM + _k0 + akb);                         \
    } while (0)

    GLOAD(0, 0); CP_COMMIT();
    GLOAD(1, 1); CP_COMMIT();
    GLOAD(2, 2); CP_COMMIT();

    for (int t = 0; t < NT; ++t) {
        CP_WAIT2();            // tile t resident (groups are 1:1 with tiles)
        __syncthreads();       // all warps past compute(t-1); tile t visible
        if (t + 3 < NT) GLOAD(t + 3, (t + 3) & 3);
        CP_COMMIT();           // commit every iter -> uniform group count

        int buf = t & 3;
        uint32_t a_sm = a_sm0 + buf * GSTAGE_B;
        uint32_t w_sm = w_sm0 + buf * GSTAGE_B;
        unsigned afr[2][4];
        #pragma unroll
        for (int mi = 0; mi < 2; ++mi) {
            uint32_t addr = a_sm + (uint32_t)(((wr * 32 + mi * 16 + lrow) * SA + lcol) * 2);
            ldsm_x4(afr[mi][0], afr[mi][1], afr[mi][2], afr[mi][3], addr);
        }
        unsigned bfr[8][2];
        #pragma unroll
        for (int p4 = 0; p4 < 4; ++p4) {
            uint32_t addr = w_sm + (uint32_t)(((wc * 64 + p4 * 16 + lrow) * SA + lcol) * 2);
            ldsm_x4(bfr[2 * p4][0], bfr[2 * p4 + 1][0],
                    bfr[2 * p4][1], bfr[2 * p4 + 1][1], addr);
        }
        #pragma unroll
        for (int mi = 0; mi < 2; ++mi)
            #pragma unroll
            for (int ni = 0; ni < 8; ++ni)
                mma_f16(acc[mi][ni], afr[mi], bfr[ni]);
    }

    // epilogue
    #pragma unroll
    for (int mi = 0; mi < 2; ++mi) {
        #pragma unroll
        for (int half = 0; half < 2; ++half) {
            int grow = i0 + wr * 32 + mi * 16 + r4 + half * 8;
            if (grow >= NN) continue;
            #pragma unroll
            for (int ni = 0; ni < 8; ++ni) {
                int gcol = j0 + wc * 64 + ni * 8 + c4 * 2;
                if (gcol >= Nout) continue;
                float v0 = acc[mi][ni][half * 2 + 0] + (bias ? bias[gcol] : 0.f);
                float v1 = acc[mi][ni][half * 2 + 1] + (bias ? bias[gcol + 1] : 0.f);
                if (RELU) { v0 = fmaxf(v0, 0.f); v1 = fmaxf(v1, 0.f); }
                if (HALF_OUT) {
                    __half2 hv = __floats2half2_rn(v0, v1);
                    *reinterpret_cast<__half2*>(Ch + (size_t)grow * Nout + gcol) = hv;
                } else {
                    *reinterpret_cast<float2*>(Cf + (size_t)grow * Nout + gcol) =
                        make_float2(v0, v1);
                }
            }
        }
    }
}

// ------- layer-2 tail: fp16 gather (80B/edge) + bias + log_softmax -----------
__global__ void agg40h_lsm_k(const float* __restrict__ b2, float* __restrict__ out) {
    int node = (int)((blockIdx.x * blockDim.x + threadIdx.x) >> 5);
    if (node >= NN) return;
    int lane = threadIdx.x & 31;
    bool act = (lane < 5);
    int beg = g_rowptr[node], end = g_rowptr[node + 1];
    float s[8];
    #pragma unroll
    for (int q = 0; q < 8; ++q) s[q] = 0.f;
    int e = beg;
    for (; e + 3 < end; e += 4) {
        int i0 = g_col[e], i1 = g_col[e + 1], i2 = g_col[e + 2], i3 = g_col[e + 3];
        if (act) {
            uint4 v0 = __ldg(reinterpret_cast<const uint4*>(g_zh + (size_t)i0 * 80) + lane);
            uint4 v1 = __ldg(reinterpret_cast<const uint4*>(g_zh + (size_t)i1 * 80) + lane);
            uint4 v2 = __ldg(reinterpret_cast<const uint4*>(g_zh + (size_t)i2 * 80) + lane);
            uint4 v3 = __ldg(reinterpret_cast<const uint4*>(g_zh + (size_t)i3 * 80) + lane);
            acc8(s, v0); acc8(s, v1); acc8(s, v2); acc8(s, v3);
        }
    }
    for (; e < end; ++e) {
        int i0 = g_col[e];
        if (act) {
            uint4 v0 = __ldg(reinterpret_cast<const uint4*>(g_zh + (size_t)i0 * 80) + lane);
            acc8(s, v0);
        }
    }
    float v[8];
    float mymax = -INFINITY;
    if (act) {
        float inv = g_invdeg[node];
        float rf[8];
        #pragma unroll
        for (int q = 0; q < 8; ++q) rf[q] = 0.f;
        uint4 rv = __ldg(reinterpret_cast<const uint4*>(g_zh + (size_t)node * 80 + 40) + lane);
        acc8(rf, rv);
        float4 bb0 = *reinterpret_cast<const float4*>(b2 + 8 * lane);
        float4 bb1 = *reinterpret_cast<const float4*>(b2 + 8 * lane + 4);
        float bb[8] = {bb0.x, bb0.y, bb0.z, bb0.w, bb1.x, bb1.y, bb1.z, bb1.w};
        #pragma unroll
        for (int q = 0; q < 8; ++q) {
            v[q] = s[q] * inv + rf[q] + bb[q];
            mymax = fmaxf(mymax, v[q]);
        }
    }
    #pragma unroll
    for (int off = 16; off > 0; off >>= 1)
        mymax = fmaxf(mymax, __shfl_xor_sync(0xffffffffu, mymax, off));
    float se = 0.f;
    if (act) {
        #pragma unroll
        for (int q = 0; q < 8; ++q) se += expf(v[q] - mymax);
    }
    #pragma unroll
    for (int off = 16; off > 0; off >>= 1)
        se += __shfl_xor_sync(0xffffffffu, se, off);
    float ls = mymax + logf(se);
    if (act) {
        float4 o0 = make_float4(v[0] - ls, v[1] - ls, v[2] - ls, v[3] - ls);
        float4 o1 = make_float4(v[4] - ls, v[5] - ls, v[6] - ls, v[7] - ls);
        float* po = out + (size_t)node * DOUT + 8 * lane;
        *reinterpret_cast<float4*>(po) = o0;
        *reinterpret_cast<float4*>(po + 4) = o1;
    }
}

// ---------------- launch -----------------------------------------------------
extern "C" void kernel_launch(void* const* d_in, const int* in_sizes, int n_in,
                              void* d_out, int out_size) {
    const float* x   = (const float*)d_in[0];
    const int*   ei  = (const int*)d_in[1];
    const int*   src = ei;
    const int*   dst = ei + NE;
    const float* Wl0 = (const float*)d_in[2];
    const float* Wr0 = (const float*)d_in[3];
    const float* b0  = (const float*)d_in[4];
    const float* Wl1 = (const float*)d_in[5];
    const float* Wr1 = (const float*)d_in[6];
    const float* b1  = (const float*)d_in[7];
    const float* Wl2 = (const float*)d_in[8];
    const float* Wr2 = (const float*)d_in[9];
    const float* b2  = (const float*)d_in[10];
    float* out = (float*)d_out;

    __half *p_xh, *p_meanh, *p_h0h, *p_h1h, *p_zh, *p_Wl0h, *p_Wr0h, *p_Wl1h, *p_Wr1h, *p_W2h;
    cudaGetSymbolAddress((void**)&p_xh, g_xh);
    cudaGetSymbolAddress((void**)&p_meanh, g_meanh);
    cudaGetSymbolAddress((void**)&p_h0h, g_h0h);
    cudaGetSymbolAddress((void**)&p_h1h, g_h1h);
    cudaGetSymbolAddress((void**)&p_zh, g_zh);
    cudaGetSymbolAddress((void**)&p_Wl0h, g_Wl0h);
    cudaGetSymbolAddress((void**)&p_Wr0h, g_Wr0h);
    cudaGetSymbolAddress((void**)&p_Wl1h, g_Wl1h);
    cudaGetSymbolAddress((void**)&p_Wr1h, g_Wr1h);
    cudaGetSymbolAddress((void**)&p_W2h, g_W2h);

    static int smem_set = 0;
    if (!smem_set) {
        cudaFuncSetAttribute(gemm_f16_k<true, true>,
                             cudaFuncAttributeMaxDynamicSharedMemorySize, GSMEM_TOTAL);
        cudaFuncSetAttribute(gemm_f16_k<false, true>,
                             cudaFuncAttributeMaxDynamicSharedMemorySize, GSMEM_TOTAL);
        smem_set = 1;
    }

    // prep (conv + zero + packs) and CSR build
    prep_k<<<(PREP_TOTAL + 255) / 256, 256>>>(x, Wl0, Wr0, Wl1, Wr1, Wl2, Wr2);
    count_deg_k<<<(NE + 255) / 256, 256>>>(dst);
    scan1_k<<<NB1, 512>>>();
    scan2_k<<<1, 256>>>();
    scan3_k<<<(NN + 255) / 256, 256>>>();
    fill_csr_k<<<(NE + 255) / 256, 256>>>(src, dst);

    dim3 gmain((NN + 127) / 128, 2);   // Nout=256
    dim3 gz((NN + 127) / 128, 1);      // Nout=80
    int aggBlocks = (NN * 32 + 255) / 256;

    // layer 0
    aggregate_h_k<<<aggBlocks, 256>>>(p_xh);
    gemm_f16_k<true, true><<<gmain, 256, GSMEM_TOTAL>>>(
        p_meanh, p_xh, p_Wl0h, p_Wr0h, b0, p_h0h, nullptr, DIM, 2);
    // layer 1
    aggregate_h_k<<<aggBlocks, 256>>>(p_h0h);
    gemm_f16_k<true, true><<<gmain, 256, GSMEM_TOTAL>>>(
        p_meanh, p_h0h, p_Wl1h, p_Wr1h, b1, p_h1h, nullptr, DIM, 2);
    // layer 2: project to 80-dim fp16 first (linearity), then aggregate + softmax
    gemm_f16_k<false, true><<<gz, 256, GSMEM_TOTAL>>>(
        p_h1h, nullptr, p_W2h, nullptr, nullptr, p_zh, nullptr, 80, 1);
    agg40h_lsm_k<<<aggBlocks, 256>>>(b2, out);
}

// round 12
// speedup vs baseline: 1.1228x; 1.1228x over previous
#include <cuda_runtime.h>
#include <cuda_fp16.h>
#include <math.h>
#include <stdint.h>

#define NN   100000
#define NE   1600000
#define DIM  256
#define DOUT 40

// ---------------- scratch (static device globals; no runtime alloc) ----------
__device__ int    g_deg[NN];
__device__ int    g_cursor[NN];
__device__ int    g_rowptr[NN + 1];
__device__ int    g_col[NE];
__device__ int    g_bsum[256];
__device__ float  g_invdeg[NN];
__device__ __half g_xh[(size_t)NN * DIM];
__device__ __half g_meanh[(size_t)NN * DIM];
__device__ __half g_h0h[(size_t)NN * DIM];
__device__ __half g_h1h[(size_t)NN * DIM];
__device__ __half g_rh[(size_t)NN * DIM];      // root-GEMM partial  R = h@Wr + b
__device__ __half g_zh[(size_t)NN * 80];       // layer-2 projected [yl(40)|yr(40)]
__device__ __half g_Wl0h[DIM * DIM];           // transposed [n][k] fp16
__device__ __half g_Wr0h[DIM * DIM];
__device__ __half g_Wl1h[DIM * DIM];
__device__ __half g_Wr1h[DIM * DIM];
__device__ __half g_W2h[80 * DIM];             // [n(80)][k(256)]

// ---------------- prep: conv_x + all weight packs (deg zeroing separate) -----
#define PREP_TOTAL 6682624
__global__ void prep_k(const float* __restrict__ x,
                       const float* __restrict__ Wl0, const float* __restrict__ Wr0,
                       const float* __restrict__ Wl1, const float* __restrict__ Wr1,
                       const float* __restrict__ Wl2, const float* __restrict__ Wr2) {
    int i = blockIdx.x * blockDim.x + threadIdx.x;
    if (i < 6400000) {
        float4 v = *reinterpret_cast<const float4*>(x + (size_t)i * 4);
        __half2 h0 = __floats2half2_rn(v.x, v.y);
        __half2 h1 = __floats2half2_rn(v.z, v.w);
        uint2 pk;
        pk.x = *reinterpret_cast<unsigned*>(&h0);
        pk.y = *reinterpret_cast<unsigned*>(&h1);
        *reinterpret_cast<uint2*>(g_xh + (size_t)i * 4) = pk;
    } else if (i < 6662144) {
        int j = i - 6400000;
        int w = j >> 16;
        int r = j & 65535;
        const float* W = (w == 0) ? Wl0 : (w == 1) ? Wr0 : (w == 2) ? Wl1 : Wr1;
        __half* o = (w == 0) ? g_Wl0h : (w == 1) ? g_Wr0h : (w == 2) ? g_Wl1h : g_Wr1h;
        int n = r >> 8, k = r & 255;
        o[(size_t)n * DIM + k] = __float2half_rn(W[(size_t)k * DIM + n]);
    } else if (i < PREP_TOTAL) {
        int j = i - 6662144;
        int w = j / 10240, r = j % 10240;
        const float* W = w ? Wr2 : Wl2;
        int n = r >> 8, k = r & 255;
        g_W2h[(size_t)(w * 40 + n) * DIM + k] = __float2half_rn(W[(size_t)k * DOUT + n]);
    }
}

// ---------------- CSR build --------------------------------------------------
__global__ void zero_deg_k() {
    int i = blockIdx.x * blockDim.x + threadIdx.x;
    if (i < NN) g_deg[i] = 0;
}

__global__ void count_deg_k(const int* __restrict__ dst) {
    int e = blockIdx.x * blockDim.x + threadIdx.x;
    if (e < NE) atomicAdd(&g_deg[dst[e]], 1);
}

#define NB1 196   // ceil(NN / 512)
__global__ void scan1_k() {
    __shared__ int wsum[16];
    int tid = threadIdx.x, lane = tid & 31, wid = tid >> 5;
    int i = blockIdx.x * 512 + tid;
    int v = (i < NN) ? g_deg[i] : 0;
    int x = v;
    #pragma unroll
    for (int off = 1; off < 32; off <<= 1) {
        int t = __shfl_up_sync(0xffffffffu, x, off);
        if (lane >= off) x += t;
    }
    if (lane == 31) wsum[wid] = x;
    __syncthreads();
    if (wid == 0 && lane < 16) {
        int w = wsum[lane];
        #pragma unroll
        for (int off = 1; off < 16; off <<= 1) {
            int t = __shfl_up_sync(0x0000ffffu, w, off);
            if (lane >= off) w += t;
        }
        wsum[lane] = w;
    }
    __syncthreads();
    int excl = x - v + ((wid > 0) ? wsum[wid - 1] : 0);
    if (i < NN) g_rowptr[i] = excl;
    if (tid == 0) g_bsum[blockIdx.x] = wsum[15];
}

__global__ void scan2_k() {
    __shared__ int sm[256];
    int t = threadIdx.x;
    int v = (t < NB1) ? g_bsum[t] : 0;
    sm[t] = v;
    __syncthreads();
    #pragma unroll
    for (int off = 1; off < 256; off <<= 1) {
        int add = (t >= off) ? sm[t - off] : 0;
        __syncthreads();
        sm[t] += add;
        __syncthreads();
    }
    if (t < NB1) g_bsum[t] = sm[t] - v;
    if (t == NB1 - 1) g_rowptr[NN] = sm[t];
}

__global__ void scan3_k() {
    int i = blockIdx.x * blockDim.x + threadIdx.x;
    if (i < NN) {
        int e = g_rowptr[i] + g_bsum[i >> 9];
        g_rowptr[i] = e;
        g_cursor[i] = e;
        int d = g_deg[i];
        g_invdeg[i] = 1.0f / (float)((d > 1) ? d : 1);
    }
}

__global__ void fill_csr_k(const int* __restrict__ src, const int* __restrict__ dst) {
    int e = blockIdx.x * blockDim.x + threadIdx.x;
    if (e < NE) {
        int d = dst[e];
        int p = atomicAdd(&g_cursor[d], 1);
        g_col[p] = src[e];
    }
}

// ---------------- aggregation (fp16 gather, fp32 accumulate) -----------------
__device__ __forceinline__ void acc8(float* s, uint4 v) {
    __half2 a = *reinterpret_cast<__half2*>(&v.x);
    __half2 b = *reinterpret_cast<__half2*>(&v.y);
    __half2 c = *reinterpret_cast<__half2*>(&v.z);
    __half2 d = *reinterpret_cast<__half2*>(&v.w);
    float2 fa = __half22float2(a), fb = __half22float2(b);
    float2 fc = __half22float2(c), fd = __half22float2(d);
    s[0] += fa.x; s[1] += fa.y; s[2] += fb.x; s[3] += fb.y;
    s[4] += fc.x; s[5] += fc.y; s[6] += fd.x; s[7] += fd.y;
}

__global__ void aggregate_h_k(const __half* __restrict__ h) {
    int node = (int)((blockIdx.x * blockDim.x + threadIdx.x) >> 5);
    if (node >= NN) return;
    int lane = threadIdx.x & 31;
    int beg = g_rowptr[node], end = g_rowptr[node + 1];
    float s[8];
    #pragma unroll
    for (int q = 0; q < 8; ++q) s[q] = 0.f;
    int e = beg;
    for (; e + 3 < end; e += 4) {
        int i0 = g_col[e], i1 = g_col[e + 1], i2 = g_col[e + 2], i3 = g_col[e + 3];
        uint4 v0 = __ldg(reinterpret_cast<const uint4*>(h + (size_t)i0 * DIM) + lane);
        uint4 v1 = __ldg(reinterpret_cast<const uint4*>(h + (size_t)i1 * DIM) + lane);
        uint4 v2 = __ldg(reinterpret_cast<const uint4*>(h + (size_t)i2 * DIM) + lane);
        uint4 v3 = __ldg(reinterpret_cast<const uint4*>(h + (size_t)i3 * DIM) + lane);
        acc8(s, v0); acc8(s, v1); acc8(s, v2); acc8(s, v3);
    }
    for (; e < end; ++e) {
        int i0 = g_col[e];
        uint4 v0 = __ldg(reinterpret_cast<const uint4*>(h + (size_t)i0 * DIM) + lane);
        acc8(s, v0);
    }
    float inv = g_invdeg[node];
    __half2 o0 = __floats2half2_rn(s[0] * inv, s[1] * inv);
    __half2 o1 = __floats2half2_rn(s[2] * inv, s[3] * inv);
    __half2 o2 = __floats2half2_rn(s[4] * inv, s[5] * inv);
    __half2 o3 = __floats2half2_rn(s[6] * inv, s[7] * inv);
    uint4 pk;
    pk.x = *reinterpret_cast<unsigned*>(&o0);
    pk.y = *reinterpret_cast<unsigned*>(&o1);
    pk.z = *reinterpret_cast<unsigned*>(&o2);
    pk.w = *reinterpret_cast<unsigned*>(&o3);
    *(reinterpret_cast<uint4*>(g_meanh + (size_t)node * DIM) + lane) = pk;
}

// ---------------- fp16 tensor-core GEMM (m16n8k16 + ldmatrix), K=256 ---------
__device__ __forceinline__ uint32_t smem_u32(const void* p) {
    uint32_t a;
    asm("{ .reg .u64 t; cvta.to.shared.u64 t, %1; cvt.u32.u64 %0, t; }"
        : "=r"(a) : "l"(p));
    return a;
}

__device__ __forceinline__ void mma_f16(float* d, const unsigned* a, const unsigned* b) {
    asm volatile(
        "mma.sync.aligned.m16n8k16.row.col.f32.f16.f16.f32 "
        "{%0,%1,%2,%3}, {%4,%5,%6,%7}, {%8,%9}, {%0,%1,%2,%3};"
        : "+f"(d[0]), "+f"(d[1]), "+f"(d[2]), "+f"(d[3])
        : "r"(a[0]), "r"(a[1]), "r"(a[2]), "r"(a[3]),
          "r"(b[0]), "r"(b[1]));
}

__device__ __forceinline__ void ldsm_x4(unsigned& r0, unsigned& r1,
                                        unsigned& r2, unsigned& r3, uint32_t addr) {
    asm volatile("ldmatrix.sync.aligned.m8n8.x4.shared.b16 {%0,%1,%2,%3}, [%4];"
                 : "=r"(r0), "=r"(r1), "=r"(r2), "=r"(r3) : "r"(addr));
}

// C = A@W^T (+bias) (+R) (+relu); A fp16 [row][k] stride DIM, W fp16 [n][k] stride DIM.
// BM=128 BN=128 BK=16, 256 threads = 8 warps (4x2), warp tile 32x64.
#define SA 24
template<bool RELU, bool HALF_OUT, bool ADD_R>
__global__ __launch_bounds__(256) void gemm_f16_k(
    const __half* __restrict__ A0, const __half* __restrict__ W0,
    const __half* __restrict__ R, const float* __restrict__ bias,
    __half* __restrict__ Ch, float* __restrict__ Cf, int Nout)
{
    __shared__ __align__(16) __half As[2][128 * SA];
    __shared__ __align__(16) __half Ws[2][128 * SA];
    int tid = threadIdx.x;
    int lane = tid & 31, wid = tid >> 5;
    int wr = wid >> 1, wc = wid & 1;
    int i0 = blockIdx.x * 128, j0 = blockIdx.y * 128;

    int arow = tid >> 1, akb = (tid & 1) << 3;
    int gi = i0 + arow; if (gi >= NN) gi = NN - 1;
    const bool w_ok = (j0 + arow < Nout);

    float acc[2][8][4];
    #pragma unroll
    for (int mi = 0; mi < 2; ++mi)
        #pragma unroll
        for (int ni = 0; ni < 8; ++ni)
            #pragma unroll
            for (int q = 0; q < 4; ++q) acc[mi][ni][q] = 0.f;

    const int lrow = lane & 15;
    const int lcol = (lane >> 4) << 3;
    const uint32_t a_sm0 = smem_u32(&As[0][0]);
    const uint32_t w_sm0 = smem_u32(&Ws[0][0]);
    const uint32_t bufstride = 128 * SA * 2;
    const int r4 = lane >> 2, c4 = lane & 3;

    // prologue: k-tile 0 -> buf 0
    {
        uint4 ra = *reinterpret_cast<const uint4*>(A0 + (size_t)gi * DIM + akb);
        uint4 rw = make_uint4(0, 0, 0, 0);
        if (w_ok) rw = *reinterpret_cast<const uint4*>(W0 + (size_t)(j0 + arow) * DIM + akb);
        *reinterpret_cast<uint4*>(&As[0][arow * SA + akb]) = ra;
        *reinterpret_cast<uint4*>(&Ws[0][arow * SA + akb]) = rw;
    }
    __syncthreads();

    int buf = 0;
    for (int k0 = 16; k0 <= DIM; k0 += 16) {
        uint4 na, nw;
        bool have_next = (k0 < DIM);
        if (have_next) {
            na = *reinterpret_cast<const uint4*>(A0 + (size_t)gi * DIM + k0 + akb);
            nw = make_uint4(0, 0, 0, 0);
            if (w_ok) nw = *reinterpret_cast<const uint4*>(W0 + (size_t)(j0 + arow) * DIM + k0 + akb);
        }

        uint32_t a_sm = a_sm0 + buf * bufstride;
        uint32_t w_sm = w_sm0 + buf * bufstride;
        unsigned afr[2][4];
        #pragma unroll
        for (int mi = 0; mi < 2; ++mi) {
            uint32_t addr = a_sm + (uint32_t)(((wr * 32 + mi * 16 + lrow) * SA + lcol) * 2);
            ldsm_x4(afr[mi][0], afr[mi][1], afr[mi][2], afr[mi][3], addr);
        }
        unsigned bfr[8][2];
        #pragma unroll
        for (int p4 = 0; p4 < 4; ++p4) {
            uint32_t addr = w_sm + (uint32_t)(((wc * 64 + p4 * 16 + lrow) * SA + lcol) * 2);
            ldsm_x4(bfr[2 * p4][0], bfr[2 * p4 + 1][0],
                    bfr[2 * p4][1], bfr[2 * p4 + 1][1], addr);
        }
        #pragma unroll
        for (int mi = 0; mi < 2; ++mi)
            #pragma unroll
            for (int ni = 0; ni < 8; ++ni)
                mma_f16(acc[mi][ni], afr[mi], bfr[ni]);

        if (have_next) {
            int nb = buf ^ 1;
            *reinterpret_cast<uint4*>(&As[nb][arow * SA + akb]) = na;
            *reinterpret_cast<uint4*>(&Ws[nb][arow * SA + akb]) = nw;
            __syncthreads();
            buf = nb;
        }
    }

    // epilogue
    #pragma unroll
    for (int mi = 0; mi < 2; ++mi) {
        #pragma unroll
        for (int half = 0; half < 2; ++half) {
            int grow = i0 + wr * 32 + mi * 16 + r4 + half * 8;
            if (grow >= NN) continue;
            #pragma unroll
            for (int ni = 0; ni < 8; ++ni) {
                int gcol = j0 + wc * 64 + ni * 8 + c4 * 2;
                if (gcol >= Nout) continue;
                float v0 = acc[mi][ni][half * 2 + 0] + (bias ? bias[gcol] : 0.f);
                float v1 = acc[mi][ni][half * 2 + 1] + (bias ? bias[gcol + 1] : 0.f);
                if (ADD_R) {
                    __half2 rv = *reinterpret_cast<const __half2*>(
                        R + (size_t)grow * Nout + gcol);
                    float2 rf = __half22float2(rv);
                    v0 += rf.x; v1 += rf.y;
                }
                if (RELU) { v0 = fmaxf(v0, 0.f); v1 = fmaxf(v1, 0.f); }
                if (HALF_OUT) {
                    __half2 hv = __floats2half2_rn(v0, v1);
                    *reinterpret_cast<__half2*>(Ch + (size_t)grow * Nout + gcol) = hv;
                } else {
                    *reinterpret_cast<float2*>(Cf + (size_t)grow * Nout + gcol) =
                        make_float2(v0, v1);
                }
            }
        }
    }
}

// ------- layer-2 tail: fp16 gather (80B/edge) + bias + log_softmax -----------
__global__ void agg40h_lsm_k(const float* __restrict__ b2, float* __restrict__ out) {
    int node = (int)((blockIdx.x * blockDim.x + threadIdx.x) >> 5);
    if (node >= NN) return;
    int lane = threadIdx.x & 31;
    bool act = (lane < 5);
    int beg = g_rowptr[node], end = g_rowptr[node + 1];
    float s[8];
    #pragma unroll
    for (int q = 0; q < 8; ++q) s[q] = 0.f;
    int e = beg;
    for (; e + 3 < end; e += 4) {
        int i0 = g_col[e], i1 = g_col[e + 1], i2 = g_col[e + 2], i3 = g_col[e + 3];
        if (act) {
            uint4 v0 = __ldg(reinterpret_cast<const uint4*>(g_zh + (size_t)i0 * 80) + lane);
            uint4 v1 = __ldg(reinterpret_cast<const uint4*>(g_zh + (size_t)i1 * 80) + lane);
            uint4 v2 = __ldg(reinterpret_cast<const uint4*>(g_zh + (size_t)i2 * 80) + lane);
            uint4 v3 = __ldg(reinterpret_cast<const uint4*>(g_zh + (size_t)i3 * 80) + lane);
            acc8(s, v0); acc8(s, v1); acc8(s, v2); acc8(s, v3);
        }
    }
    for (; e < end; ++e) {
        int i0 = g_col[e];
        if (act) {
            uint4 v0 = __ldg(reinterpret_cast<const uint4*>(g_zh + (size_t)i0 * 80) + lane);
            acc8(s, v0);
        }
    }
    float v[8];
    float mymax = -INFINITY;
    if (act) {
        float inv = g_invdeg[node];
        float rf[8];
        #pragma unroll
        for (int q = 0; q < 8; ++q) rf[q] = 0.f;
        uint4 rv = __ldg(reinterpret_cast<const uint4*>(g_zh + (size_t)node * 80 + 40) + lane);
        acc8(rf, rv);
        float4 bb0 = *reinterpret_cast<const float4*>(b2 + 8 * lane);
        float4 bb1 = *reinterpret_cast<const float4*>(b2 + 8 * lane + 4);
        float bb[8] = {bb0.x, bb0.y, bb0.z, bb0.w, bb1.x, bb1.y, bb1.z, bb1.w};
        #pragma unroll
        for (int q = 0; q < 8; ++q) {
            v[q] = s[q] * inv + rf[q] + bb[q];
            mymax = fmaxf(mymax, v[q]);
        }
    }
    #pragma unroll
    for (int off = 16; off > 0; off >>= 1)
        mymax = fmaxf(mymax, __shfl_xor_sync(0xffffffffu, mymax, off));
    float se = 0.f;
    if (act) {
        #pragma unroll
        for (int q = 0; q < 8; ++q) se += expf(v[q] - mymax);
    }
    #pragma unroll
    for (int off = 16; off > 0; off >>= 1)
        se += __shfl_xor_sync(0xffffffffu, se, off);
    float ls = mymax + logf(se);
    if (act) {
        float4 o0 = make_float4(v[0] - ls, v[1] - ls, v[2] - ls, v[3] - ls);
        float4 o1 = make_float4(v[4] - ls, v[5] - ls, v[6] - ls, v[7] - ls);
        float* po = out + (size_t)node * DOUT + 8 * lane;
        *reinterpret_cast<float4*>(po) = o0;
        *reinterpret_cast<float4*>(po + 4) = o1;
    }
}

// ---------------- launch (fork/join across two streams) ----------------------
extern "C" void kernel_launch(void* const* d_in, const int* in_sizes, int n_in,
                              void* d_out, int out_size) {
    const float* x   = (const float*)d_in[0];
    const int*   ei  = (const int*)d_in[1];
    const int*   src = ei;
    const int*   dst = ei + NE;
    const float* Wl0 = (const float*)d_in[2];
    const float* Wr0 = (const float*)d_in[3];
    const float* b0  = (const float*)d_in[4];
    const float* Wl1 = (const float*)d_in[5];
    const float* Wr1 = (const float*)d_in[6];
    const float* b1  = (const float*)d_in[7];
    const float* Wl2 = (const float*)d_in[8];
    const float* Wr2 = (const float*)d_in[9];
    const float* b2  = (const float*)d_in[10];
    float* out = (float*)d_out;

    __half *p_xh, *p_meanh, *p_h0h, *p_h1h, *p_rh, *p_zh;
    __half *p_Wl0h, *p_Wr0h, *p_Wl1h, *p_Wr1h, *p_W2h;
    cudaGetSymbolAddress((void**)&p_xh, g_xh);
    cudaGetSymbolAddress((void**)&p_meanh, g_meanh);
    cudaGetSymbolAddress((void**)&p_h0h, g_h0h);
    cudaGetSymbolAddress((void**)&p_h1h, g_h1h);
    cudaGetSymbolAddress((void**)&p_rh, g_rh);
    cudaGetSymbolAddress((void**)&p_zh, g_zh);
    cudaGetSymbolAddress((void**)&p_Wl0h, g_Wl0h);
    cudaGetSymbolAddress((void**)&p_Wr0h, g_Wr0h);
    cudaGetSymbolAddress((void**)&p_Wl1h, g_Wl1h);
    cudaGetSymbolAddress((void**)&p_Wr1h, g_Wr1h);
    cudaGetSymbolAddress((void**)&p_W2h, g_W2h);

    static cudaStream_t s2 = nullptr;
    static cudaEvent_t evFork, evP, evAgg0, evH0, evAgg1;
    if (!s2) {
        cudaStreamCreateWithFlags(&s2, cudaStreamNonBlocking);
        cudaEventCreateWithFlags(&evFork, cudaEventDisableTiming);
        cudaEventCreateWithFlags(&evP, cudaEventDisableTiming);
        cudaEventCreateWithFlags(&evAgg0, cudaEventDisableTiming);
        cudaEventCreateWithFlags(&evH0, cudaEventDisableTiming);
        cudaEventCreateWithFlags(&evAgg1, cudaEventDisableTiming);
    }

    dim3 gmain((NN + 127) / 128, 2);   // Nout=256
    dim3 gz((NN + 127) / 128, 1);      // Nout=80
    int aggBlocks = (NN * 32 + 255) / 256;

    // ---- fork: stream B builds CSR while legacy does prep + root0 ----
    cudaEventRecord(evFork, 0);
    cudaStreamWaitEvent(s2, evFork, 0);

    // stream B: CSR chain
    zero_deg_k<<<(NN + 255) / 256, 256, 0, s2>>>();
    count_deg_k<<<(NE + 255) / 256, 256, 0, s2>>>(dst);
    scan1_k<<<NB1, 512, 0, s2>>>();
    scan2_k<<<1, 256, 0, s2>>>();
    scan3_k<<<(NN + 255) / 256, 256, 0, s2>>>();
    fill_csr_k<<<(NE + 255) / 256, 256, 0, s2>>>(src, dst);

    // legacy: prep, then root GEMM of layer 0 (independent of aggregation)
    prep_k<<<(PREP_TOTAL + 255) / 256, 256>>>(x, Wl0, Wr0, Wl1, Wr1, Wl2, Wr2);
    cudaEventRecord(evP, 0);
    gemm_f16_k<false, true, false><<<gmain, 256>>>(
        p_xh, p_Wr0h, nullptr, b0, p_rh, nullptr, DIM);   // R0 = x@Wr0 + b0

    // stream B: aggregate layer 0 (needs CSR [stream order] + xh [evP])
    cudaStreamWaitEvent(s2, evP, 0);
    aggregate_h_k<<<aggBlocks, 256, 0, s2>>>(p_xh);
    cudaEventRecord(evAgg0, s2);

    // legacy: mean GEMM layer 0 (needs root0 [stream order] + agg0 [event])
    cudaStreamWaitEvent(0, evAgg0, 0);
    gemm_f16_k<true, true, true><<<gmain, 256>>>(
        p_meanh, p_Wl0h, p_rh, nullptr, p_h0h, nullptr, DIM);
    cudaEventRecord(evH0, 0);

    // ---- layer 1 fork: agg1 (B) || root1 (legacy) ----
    cudaStreamWaitEvent(s2, evH0, 0);
    aggregate_h_k<<<aggBlocks, 256, 0, s2>>>(p_h0h);
    cudaEventRecord(evAgg1, s2);

    gemm_f16_k<false, true, false><<<gmain, 256>>>(
        p_h0h, p_Wr1h, nullptr, b1, p_rh, nullptr, DIM);  // R1 = h0@Wr1 + b1

    cudaStreamWaitEvent(0, evAgg1, 0);
    gemm_f16_k<true, true, true><<<gmain, 256>>>(
        p_meanh, p_Wl1h, p_rh, nullptr, p_h1h, nullptr, DIM);

    // layer 2: project to 80-dim fp16 (linearity), then aggregate + softmax
    gemm_f16_k<false, true, false><<<gz, 256>>>(
        p_h1h, p_W2h, nullptr, nullptr, p_zh, nullptr, 80);
    agg40h_lsm_k<<<aggBlocks, 256>>>(b2, out);
}

// round 13
// speedup vs baseline: 1.2128x; 1.0802x over previous
#include <cuda_runtime.h>
#include <cuda_fp16.h>
#include <math.h>
#include <stdint.h>

#define NN   100000
#define NE   1600000
#define DIM  256
#define DOUT 40

// ---------------- scratch (static device globals; no runtime alloc) ----------
__device__ int    g_deg[NN];
__device__ int    g_cursor[NN];
__device__ int    g_rowptr[NN + 1];
__device__ int    g_col[NE];
__device__ int    g_bsum[256];
__device__ float  g_invdeg[NN];
__device__ __half g_xh[(size_t)NN * DIM];
__device__ __half g_meanh[(size_t)NN * DIM];
__device__ __half g_h0h[(size_t)NN * DIM];
__device__ __half g_h1h[(size_t)NN * DIM];
__device__ __half g_zh[(size_t)NN * 80];       // layer-2 projected [yl(40)|yr(40)] fp16
__device__ __half g_Wl0h[DIM * DIM];           // transposed [n][k] fp16
__device__ __half g_Wr0h[DIM * DIM];
__device__ __half g_Wl1h[DIM * DIM];
__device__ __half g_Wr1h[DIM * DIM];
__device__ __half g_W2h[80 * DIM];             // [n(80)][k(256)]

// ---------------- prep: conv_x + all weight packs ----------------------------
#define PREP_TOTAL 6682624
__global__ void prep_k(const float* __restrict__ x,
                       const float* __restrict__ Wl0, const float* __restrict__ Wr0,
                       const float* __restrict__ Wl1, const float* __restrict__ Wr1,
                       const float* __restrict__ Wl2, const float* __restrict__ Wr2) {
    int i = blockIdx.x * blockDim.x + threadIdx.x;
    if (i < 6400000) {
        float4 v = *reinterpret_cast<const float4*>(x + (size_t)i * 4);
        __half2 h0 = __floats2half2_rn(v.x, v.y);
        __half2 h1 = __floats2half2_rn(v.z, v.w);
        uint2 pk;
        pk.x = *reinterpret_cast<unsigned*>(&h0);
        pk.y = *reinterpret_cast<unsigned*>(&h1);
        *reinterpret_cast<uint2*>(g_xh + (size_t)i * 4) = pk;
    } else if (i < 6662144) {
        int j = i - 6400000;
        int w = j >> 16;
        int r = j & 65535;
        const float* W = (w == 0) ? Wl0 : (w == 1) ? Wr0 : (w == 2) ? Wl1 : Wr1;
        __half* o = (w == 0) ? g_Wl0h : (w == 1) ? g_Wr0h : (w == 2) ? g_Wl1h : g_Wr1h;
        int n = r >> 8, k = r & 255;
        o[(size_t)n * DIM + k] = __float2half_rn(W[(size_t)k * DIM + n]);
    } else if (i < PREP_TOTAL) {
        int j = i - 6662144;
        int w = j / 10240, r = j % 10240;
        const float* W = w ? Wr2 : Wl2;
        int n = r >> 8, k = r & 255;
        g_W2h[(size_t)(w * 40 + n) * DIM + k] = __float2half_rn(W[(size_t)k * DOUT + n]);
    }
}

// ---------------- CSR build --------------------------------------------------
__global__ void zero_deg_k() {
    int i = blockIdx.x * blockDim.x + threadIdx.x;
    if (i < NN) g_deg[i] = 0;
}

__global__ void count_deg_k(const int* __restrict__ dst) {
    int e = blockIdx.x * blockDim.x + threadIdx.x;
    if (e < NE) atomicAdd(&g_deg[dst[e]], 1);
}

#define NB1 196   // ceil(NN / 512)
__global__ void scan1_k() {
    __shared__ int wsum[16];
    int tid = threadIdx.x, lane = tid & 31, wid = tid >> 5;
    int i = blockIdx.x * 512 + tid;
    int v = (i < NN) ? g_deg[i] : 0;
    int x = v;
    #pragma unroll
    for (int off = 1; off < 32; off <<= 1) {
        int t = __shfl_up_sync(0xffffffffu, x, off);
        if (lane >= off) x += t;
    }
    if (lane == 31) wsum[wid] = x;
    __syncthreads();
    if (wid == 0 && lane < 16) {
        int w = wsum[lane];
        #pragma unroll
        for (int off = 1; off < 16; off <<= 1) {
            int t = __shfl_up_sync(0x0000ffffu, w, off);
            if (lane >= off) w += t;
        }
        wsum[lane] = w;
    }
    __syncthreads();
    int excl = x - v + ((wid > 0) ? wsum[wid - 1] : 0);
    if (i < NN) g_rowptr[i] = excl;
    if (tid == 0) g_bsum[blockIdx.x] = wsum[15];
}

__global__ void scan2_k() {
    __shared__ int sm[256];
    int t = threadIdx.x;
    int v = (t < NB1) ? g_bsum[t] : 0;
    sm[t] = v;
    __syncthreads();
    #pragma unroll
    for (int off = 1; off < 256; off <<= 1) {
        int add = (t >= off) ? sm[t - off] : 0;
        __syncthreads();
        sm[t] += add;
        __syncthreads();
    }
    if (t < NB1) g_bsum[t] = sm[t] - v;
    if (t == NB1 - 1) g_rowptr[NN] = sm[t];
}

__global__ void scan3_k() {
    int i = blockIdx.x * blockDim.x + threadIdx.x;
    if (i < NN) {
        int e = g_rowptr[i] + g_bsum[i >> 9];
        g_rowptr[i] = e;
        g_cursor[i] = e;
        int d = g_deg[i];
        g_invdeg[i] = 1.0f / (float)((d > 1) ? d : 1);
    }
}

__global__ void fill_csr_k(const int* __restrict__ src, const int* __restrict__ dst) {
    int e = blockIdx.x * blockDim.x + threadIdx.x;
    if (e < NE) {
        int d = dst[e];
        int p = atomicAdd(&g_cursor[d], 1);
        g_col[p] = src[e];
    }
}

// ---------------- aggregation (fp16 gather, fp32 accumulate) -----------------
__device__ __forceinline__ void acc8(float* s, uint4 v) {
    __half2 a = *reinterpret_cast<__half2*>(&v.x);
    __half2 b = *reinterpret_cast<__half2*>(&v.y);
    __half2 c = *reinterpret_cast<__half2*>(&v.z);
    __half2 d = *reinterpret_cast<__half2*>(&v.w);
    float2 fa = __half22float2(a), fb = __half22float2(b);
    float2 fc = __half22float2(c), fd = __half22float2(d);
    s[0] += fa.x; s[1] += fa.y; s[2] += fb.x; s[3] += fb.y;
    s[4] += fc.x; s[5] += fc.y; s[6] += fd.x; s[7] += fd.y;
}

__global__ void aggregate_h_k(const __half* __restrict__ h) {
    int node = (int)((blockIdx.x * blockDim.x + threadIdx.x) >> 5);
    if (node >= NN) return;
    int lane = threadIdx.x & 31;
    int beg = g_rowptr[node], end = g_rowptr[node + 1];
    float s[8];
    #pragma unroll
    for (int q = 0; q < 8; ++q) s[q] = 0.f;
    int e = beg;
    for (; e + 3 < end; e += 4) {
        int i0 = g_col[e], i1 = g_col[e + 1], i2 = g_col[e + 2], i3 = g_col[e + 3];
        uint4 v0 = __ldg(reinterpret_cast<const uint4*>(h + (size_t)i0 * DIM) + lane);
        uint4 v1 = __ldg(reinterpret_cast<const uint4*>(h + (size_t)i1 * DIM) + lane);
        uint4 v2 = __ldg(reinterpret_cast<const uint4*>(h + (size_t)i2 * DIM) + lane);
        uint4 v3 = __ldg(reinterpret_cast<const uint4*>(h + (size_t)i3 * DIM) + lane);
        acc8(s, v0); acc8(s, v1); acc8(s, v2); acc8(s, v3);
    }
    for (; e < end; ++e) {
        int i0 = g_col[e];
        uint4 v0 = __ldg(reinterpret_cast<const uint4*>(h + (size_t)i0 * DIM) + lane);
        acc8(s, v0);
    }
    float inv = g_invdeg[node];
    __half2 o0 = __floats2half2_rn(s[0] * inv, s[1] * inv);
    __half2 o1 = __floats2half2_rn(s[2] * inv, s[3] * inv);
    __half2 o2 = __floats2half2_rn(s[4] * inv, s[5] * inv);
    __half2 o3 = __floats2half2_rn(s[6] * inv, s[7] * inv);
    uint4 pk;
    pk.x = *reinterpret_cast<unsigned*>(&o0);
    pk.y = *reinterpret_cast<unsigned*>(&o1);
    pk.z = *reinterpret_cast<unsigned*>(&o2);
    pk.w = *reinterpret_cast<unsigned*>(&o3);
    *(reinterpret_cast<uint4*>(g_meanh + (size_t)node * DIM) + lane) = pk;
}

// ---------------- fp16 tensor-core GEMM (m16n8k16 + ldmatrix) ----------------
__device__ __forceinline__ uint32_t smem_u32(const void* p) {
    uint32_t a;
    asm("{ .reg .u64 t; cvta.to.shared.u64 t, %1; cvt.u32.u64 %0, t; }"
        : "=r"(a) : "l"(p));
    return a;
}

__device__ __forceinline__ void mma_f16(float* d, const unsigned* a, const unsigned* b) {
    asm volatile(
        "mma.sync.aligned.m16n8k16.row.col.f32.f16.f16.f32 "
        "{%0,%1,%2,%3}, {%4,%5,%6,%7}, {%8,%9}, {%0,%1,%2,%3};"
        : "+f"(d[0]), "+f"(d[1]), "+f"(d[2]), "+f"(d[3])
        : "r"(a[0]), "r"(a[1]), "r"(a[2]), "r"(a[3]),
          "r"(b[0]), "r"(b[1]));
}

__device__ __forceinline__ void ldsm_x4(unsigned& r0, unsigned& r1,
                                        unsigned& r2, unsigned& r3, uint32_t addr) {
    asm volatile("ldmatrix.sync.aligned.m8n8.x4.shared.b16 {%0,%1,%2,%3}, [%4];"
                 : "=r"(r0), "=r"(r1), "=r"(r2), "=r"(r3) : "r"(addr));
}

// C = A0@W0^T (+ A1@W1^T) + bias; A fp16 [row][k] stride DIM, W fp16 [n][k] stride DIM.
// BM=128 BN=128 BK=16, 256 threads = 8 warps (4x2), warp tile 32x64.
#define SA 24
template<bool RELU, bool HALF_OUT>
__global__ __launch_bounds__(256) void gemm_f16_k(
    const __half* __restrict__ A0, const __half* __restrict__ A1,
    const __half* __restrict__ W0, const __half* __restrict__ W1,
    const float* __restrict__ bias,
    __half* __restrict__ Ch, float* __restrict__ Cf,
    int Nout, int nphase)
{
    __shared__ __align__(16) __half As[2][128 * SA];
    __shared__ __align__(16) __half Ws[2][128 * SA];
    int tid = threadIdx.x;
    int lane = tid & 31, wid = tid >> 5;
    int wr = wid >> 1, wc = wid & 1;
    int i0 = blockIdx.x * 128, j0 = blockIdx.y * 128;

    int arow = tid >> 1, akb = (tid & 1) << 3;
    int gi = i0 + arow; if (gi >= NN) gi = NN - 1;
    const bool w_ok = (j0 + arow < Nout);

    float acc[2][8][4];
    #pragma unroll
    for (int mi = 0; mi < 2; ++mi)
        #pragma unroll
        for (int ni = 0; ni < 8; ++ni)
            #pragma unroll
            for (int q = 0; q < 4; ++q) acc[mi][ni][q] = 0.f;

    const int lrow = lane & 15;
    const int lcol = (lane >> 4) << 3;
    const uint32_t a_sm0 = smem_u32(&As[0][0]);
    const uint32_t w_sm0 = smem_u32(&Ws[0][0]);
    const uint32_t bufstride = 128 * SA * 2;
    const int r4 = lane >> 2, c4 = lane & 3;

    for (int p = 0; p < nphase; ++p) {
        const __half* Ap = p ? A1 : A0;
        const __half* Wp = p ? W1 : W0;

        {
            uint4 ra = *reinterpret_cast<const uint4*>(Ap + (size_t)gi * DIM + akb);
            uint4 rw = make_uint4(0, 0, 0, 0);
            if (w_ok) rw = *reinterpret_cast<const uint4*>(Wp + (size_t)(j0 + arow) * DIM + akb);
            *reinterpret_cast<uint4*>(&As[0][arow * SA + akb]) = ra;
            *reinterpret_cast<uint4*>(&Ws[0][arow * SA + akb]) = rw;
        }
        __syncthreads();

        int buf = 0;
        for (int k0 = 16; k0 <= DIM; k0 += 16) {
            uint4 na, nw;
            bool have_next = (k0 < DIM);
            if (have_next) {
                na = *reinterpret_cast<const uint4*>(Ap + (size_t)gi * DIM + k0 + akb);
                nw = make_uint4(0, 0, 0, 0);
                if (w_ok) nw = *reinterpret_cast<const uint4*>(Wp + (size_t)(j0 + arow) * DIM + k0 + akb);
            }

            uint32_t a_sm = a_sm0 + buf * bufstride;
            uint32_t w_sm = w_sm0 + buf * bufstride;
            unsigned afr[2][4];
            #pragma unroll
            for (int mi = 0; mi < 2; ++mi) {
                uint32_t addr = a_sm + (uint32_t)(((wr * 32 + mi * 16 + lrow) * SA + lcol) * 2);
                ldsm_x4(afr[mi][0], afr[mi][1], afr[mi][2], afr[mi][3], addr);
            }
            unsigned bfr[8][2];
            #pragma unroll
            for (int p4 = 0; p4 < 4; ++p4) {
                uint32_t addr = w_sm + (uint32_t)(((wc * 64 + p4 * 16 + lrow) * SA + lcol) * 2);
                ldsm_x4(bfr[2 * p4][0], bfr[2 * p4 + 1][0],
                        bfr[2 * p4][1], bfr[2 * p4 + 1][1], addr);
            }
            #pragma unroll
            for (int mi = 0; mi < 2; ++mi)
                #pragma unroll
                for (int ni = 0; ni < 8; ++ni)
                    mma_f16(acc[mi][ni], afr[mi], bfr[ni]);

            if (have_next) {
                int nb = buf ^ 1;
                *reinterpret_cast<uint4*>(&As[nb][arow * SA + akb]) = na;
                *reinterpret_cast<uint4*>(&Ws[nb][arow * SA + akb]) = nw;
                __syncthreads();
                buf = nb;
            }
        }
        __syncthreads();
    }

    #pragma unroll
    for (int mi = 0; mi < 2; ++mi) {
        #pragma unroll
        for (int half = 0; half < 2; ++half) {
            int grow = i0 + wr * 32 + mi * 16 + r4 + half * 8;
            if (grow >= NN) continue;
            #pragma unroll
            for (int ni = 0; ni < 8; ++ni) {
                int gcol = j0 + wc * 64 + ni * 8 + c4 * 2;
                if (gcol >= Nout) continue;
                float v0 = acc[mi][ni][half * 2 + 0] + (bias ? bias[gcol] : 0.f);
                float v1 = acc[mi][ni][half * 2 + 1] + (bias ? bias[gcol + 1] : 0.f);
                if (RELU) { v0 = fmaxf(v0, 0.f); v1 = fmaxf(v1, 0.f); }
                if (HALF_OUT) {
                    __half2 hv = __floats2half2_rn(v0, v1);
                    *reinterpret_cast<__half2*>(Ch + (size_t)grow * Nout + gcol) = hv;
                } else {
                    *reinterpret_cast<float2*>(Cf + (size_t)grow * Nout + gcol) =
                        make_float2(v0, v1);
                }
            }
        }
    }
}

// ------- layer-2 tail: fp16 gather (80B/edge) + bias + log_softmax -----------
__global__ void agg40h_lsm_k(const float* __restrict__ b2, float* __restrict__ out) {
    int node = (int)((blockIdx.x * blockDim.x + threadIdx.x) >> 5);
    if (node >= NN) return;
    int lane = threadIdx.x & 31;
    bool act = (lane < 5);
    int beg = g_rowptr[node], end = g_rowptr[node + 1];
    float s[8];
    #pragma unroll
    for (int q = 0; q < 8; ++q) s[q] = 0.f;
    int e = beg;
    for (; e + 3 < end; e += 4) {
        int i0 = g_col[e], i1 = g_col[e + 1], i2 = g_col[e + 2], i3 = g_col[e + 3];
        if (act) {
            uint4 v0 = __ldg(reinterpret_cast<const uint4*>(g_zh + (size_t)i0 * 80) + lane);
            uint4 v1 = __ldg(reinterpret_cast<const uint4*>(g_zh + (size_t)i1 * 80) + lane);
            uint4 v2 = __ldg(reinterpret_cast<const uint4*>(g_zh + (size_t)i2 * 80) + lane);
            uint4 v3 = __ldg(reinterpret_cast<const uint4*>(g_zh + (size_t)i3 * 80) + lane);
            acc8(s, v0); acc8(s, v1); acc8(s, v2); acc8(s, v3);
        }
    }
    for (; e < end; ++e) {
        int i0 = g_col[e];
        if (act) {
            uint4 v0 = __ldg(reinterpret_cast<const uint4*>(g_zh + (size_t)i0 * 80) + lane);
            acc8(s, v0);
        }
    }
    float v[8];
    float mymax = -INFINITY;
    if (act) {
        float inv = g_invdeg[node];
        float rf[8];
        #pragma unroll
        for (int q = 0; q < 8; ++q) rf[q] = 0.f;
        uint4 rv = __ldg(reinterpret_cast<const uint4*>(g_zh + (size_t)node * 80 + 40) + lane);
        acc8(rf, rv);
        float4 bb0 = *reinterpret_cast<const float4*>(b2 + 8 * lane);
        float4 bb1 = *reinterpret_cast<const float4*>(b2 + 8 * lane + 4);
        float bb[8] = {bb0.x, bb0.y, bb0.z, bb0.w, bb1.x, bb1.y, bb1.z, bb1.w};
        #pragma unroll
        for (int q = 0; q < 8; ++q) {
            v[q] = s[q] * inv + rf[q] + bb[q];
            mymax = fmaxf(mymax, v[q]);
        }
    }
    #pragma unroll
    for (int off = 16; off > 0; off >>= 1)
        mymax = fmaxf(mymax, __shfl_xor_sync(0xffffffffu, mymax, off));
    float se = 0.f;
    if (act) {
        #pragma unroll
        for (int q = 0; q < 8; ++q) se += expf(v[q] - mymax);
    }
    #pragma unroll
    for (int off = 16; off > 0; off >>= 1)
        se += __shfl_xor_sync(0xffffffffu, se, off);
    float ls = mymax + logf(se);
    if (act) {
        float4 o0 = make_float4(v[0] - ls, v[1] - ls, v[2] - ls, v[3] - ls);
        float4 o1 = make_float4(v[4] - ls, v[5] - ls, v[6] - ls, v[7] - ls);
        float* po = out + (size_t)node * DOUT + 8 * lane;
        *reinterpret_cast<float4*>(po) = o0;
        *reinterpret_cast<float4*>(po + 4) = o1;
    }
}

// ---------------- launch -----------------------------------------------------
extern "C" void kernel_launch(void* const* d_in, const int* in_sizes, int n_in,
                              void* d_out, int out_size) {
    const float* x   = (const float*)d_in[0];
    const int*   ei  = (const int*)d_in[1];
    const int*   src = ei;
    const int*   dst = ei + NE;
    const float* Wl0 = (const float*)d_in[2];
    const float* Wr0 = (const float*)d_in[3];
    const float* b0  = (const float*)d_in[4];
    const float* Wl1 = (const float*)d_in[5];
    const float* Wr1 = (const float*)d_in[6];
    const float* b1  = (const float*)d_in[7];
    const float* Wl2 = (const float*)d_in[8];
    const float* Wr2 = (const float*)d_in[9];
    const float* b2  = (const float*)d_in[10];
    float* out = (float*)d_out;

    __half *p_xh, *p_meanh, *p_h0h, *p_h1h, *p_zh;
    __half *p_Wl0h, *p_Wr0h, *p_Wl1h, *p_Wr1h, *p_W2h;
    cudaGetSymbolAddress((void**)&p_xh, g_xh);
    cudaGetSymbolAddress((void**)&p_meanh, g_meanh);
    cudaGetSymbolAddress((void**)&p_h0h, g_h0h);
    cudaGetSymbolAddress((void**)&p_h1h, g_h1h);
    cudaGetSymbolAddress((void**)&p_zh, g_zh);
    cudaGetSymbolAddress((void**)&p_Wl0h, g_Wl0h);
    cudaGetSymbolAddress((void**)&p_Wr0h, g_Wr0h);
    cudaGetSymbolAddress((void**)&p_Wl1h, g_Wl1h);
    cudaGetSymbolAddress((void**)&p_Wr1h, g_Wr1h);
    cudaGetSymbolAddress((void**)&p_W2h, g_W2h);

    static cudaStream_t s2 = nullptr;
    static cudaEvent_t evFork, evCSR;
    if (!s2) {
        cudaStreamCreateWithFlags(&s2, cudaStreamNonBlocking);
        cudaEventCreateWithFlags(&evFork, cudaEventDisableTiming);
        cudaEventCreateWithFlags(&evCSR, cudaEventDisableTiming);
    }

    dim3 gmain((NN + 127) / 128, 2);   // Nout=256
    dim3 gz((NN + 127) / 128, 1);      // Nout=80
    int aggBlocks = (NN * 32 + 255) / 256;

    // ---- fork: CSR chain on stream B || prep on capture stream --------------
    cudaEventRecord(evFork, 0);
    cudaStreamWaitEvent(s2, evFork, 0);

    zero_deg_k<<<(NN + 255) / 256, 256, 0, s2>>>();
    count_deg_k<<<(NE + 255) / 256, 256, 0, s2>>>(dst);
    scan1_k<<<NB1, 512, 0, s2>>>();
    scan2_k<<<1, 256, 0, s2>>>();
    scan3_k<<<(NN + 255) / 256, 256, 0, s2>>>();
    fill_csr_k<<<(NE + 255) / 256, 256, 0, s2>>>(src, dst);
    cudaEventRecord(evCSR, s2);

    prep_k<<<(PREP_TOTAL + 255) / 256, 256>>>(x, Wl0, Wr0, Wl1, Wr1, Wl2, Wr2);

    // ---- join: everything below needs both prep (stream order) and CSR ------
    cudaStreamWaitEvent(0, evCSR, 0);

    // layer 0
    aggregate_h_k<<<aggBlocks, 256>>>(p_xh);
    gemm_f16_k<true, true><<<gmain, 256>>>(p_meanh, p_xh, p_Wl0h, p_Wr0h, b0,
                                           p_h0h, nullptr, DIM, 2);
    // layer 1
    aggregate_h_k<<<aggBlocks, 256>>>(p_h0h);
    gemm_f16_k<true, true><<<gmain, 256>>>(p_meanh, p_h0h, p_Wl1h, p_Wr1h, b1,
                                           p_h1h, nullptr, DIM, 2);
    // layer 2: project to 80-dim fp16 first (linearity), then aggregate + softmax
    gemm_f16_k<false, true><<<gz, 256>>>(p_h1h, nullptr, p_W2h, nullptr, nullptr,
                                         p_zh, nullptr, 80, 1);
    agg40h_lsm_k<<<aggBlocks, 256>>>(b2, out);
}

// round 14
// speedup vs baseline: 1.2321x; 1.0159x over previous
#include <cuda_runtime.h>
#include <cuda_fp16.h>
#include <math.h>
#include <stdint.h>

#define NN   100000
#define NE   1600000
#define DIM  256
#define DOUT 40

// ---------------- scratch (static device globals; no runtime alloc) ----------
__device__ int    g_deg[NN];
__device__ int    g_cursor[NN];
__device__ int    g_rowptr[NN + 1];
__device__ int    g_col[NE];
__device__ int    g_bsum[256];
__device__ float  g_invdeg[NN];
__device__ __half g_xh[(size_t)NN * DIM];
__device__ __half g_meanh[(size_t)NN * DIM];
__device__ __half g_h0h[(size_t)NN * DIM];
__device__ __half g_h1h[(size_t)NN * DIM];
__device__ __half g_zh[(size_t)NN * 80];       // layer-2 projected [yl(40)|yr(40)] fp16
__device__ __half g_Wl0h[DIM * DIM];           // transposed [n][k] fp16
__device__ __half g_Wr0h[DIM * DIM];
__device__ __half g_Wl1h[DIM * DIM];
__device__ __half g_Wr1h[DIM * DIM];
__device__ __half g_W2h[80 * DIM];             // [n(80)][k(256)]

// ---------------- prep: conv_x + all weight packs ----------------------------
#define PREP_TOTAL 6682624
__global__ void prep_k(const float* __restrict__ x,
                       const float* __restrict__ Wl0, const float* __restrict__ Wr0,
                       const float* __restrict__ Wl1, const float* __restrict__ Wr1,
                       const float* __restrict__ Wl2, const float* __restrict__ Wr2) {
    int i = blockIdx.x * blockDim.x + threadIdx.x;
    if (i < 6400000) {
        float4 v = *reinterpret_cast<const float4*>(x + (size_t)i * 4);
        __half2 h0 = __floats2half2_rn(v.x, v.y);
        __half2 h1 = __floats2half2_rn(v.z, v.w);
        uint2 pk;
        pk.x = *reinterpret_cast<unsigned*>(&h0);
        pk.y = *reinterpret_cast<unsigned*>(&h1);
        *reinterpret_cast<uint2*>(g_xh + (size_t)i * 4) = pk;
    } else if (i < 6662144) {
        int j = i - 6400000;
        int w = j >> 16;
        int r = j & 65535;
        const float* W = (w == 0) ? Wl0 : (w == 1) ? Wr0 : (w == 2) ? Wl1 : Wr1;
        __half* o = (w == 0) ? g_Wl0h : (w == 1) ? g_Wr0h : (w == 2) ? g_Wl1h : g_Wr1h;
        int n = r >> 8, k = r & 255;
        o[(size_t)n * DIM + k] = __float2half_rn(W[(size_t)k * DIM + n]);
    } else if (i < PREP_TOTAL) {
        int j = i - 6662144;
        int w = j / 10240, r = j % 10240;
        const float* W = w ? Wr2 : Wl2;
        int n = r >> 8, k = r & 255;
        g_W2h[(size_t)(w * 40 + n) * DIM + k] = __float2half_rn(W[(size_t)k * DOUT + n]);
    }
}

// ---------------- CSR build --------------------------------------------------
__global__ void zero_deg_k() {
    int i = blockIdx.x * blockDim.x + threadIdx.x;
    if (i < NN) g_deg[i] = 0;
}

__global__ void count_deg_k(const int* __restrict__ dst) {
    int e = blockIdx.x * blockDim.x + threadIdx.x;
    if (e < NE) atomicAdd(&g_deg[dst[e]], 1);
}

#define NB1 196   // ceil(NN / 512)
__global__ void scan1_k() {
    __shared__ int wsum[16];
    int tid = threadIdx.x, lane = tid & 31, wid = tid >> 5;
    int i = blockIdx.x * 512 + tid;
    int v = (i < NN) ? g_deg[i] : 0;
    int x = v;
    #pragma unroll
    for (int off = 1; off < 32; off <<= 1) {
        int t = __shfl_up_sync(0xffffffffu, x, off);
        if (lane >= off) x += t;
    }
    if (lane == 31) wsum[wid] = x;
    __syncthreads();
    if (wid == 0 && lane < 16) {
        int w = wsum[lane];
        #pragma unroll
        for (int off = 1; off < 16; off <<= 1) {
            int t = __shfl_up_sync(0x0000ffffu, w, off);
            if (lane >= off) w += t;
        }
        wsum[lane] = w;
    }
    __syncthreads();
    int excl = x - v + ((wid > 0) ? wsum[wid - 1] : 0);
    if (i < NN) g_rowptr[i] = excl;
    if (tid == 0) g_bsum[blockIdx.x] = wsum[15];
}

__global__ void scan2_k() {
    __shared__ int sm[256];
    int t = threadIdx.x;
    int v = (t < NB1) ? g_bsum[t] : 0;
    sm[t] = v;
    __syncthreads();
    #pragma unroll
    for (int off = 1; off < 256; off <<= 1) {
        int add = (t >= off) ? sm[t - off] : 0;
        __syncthreads();
        sm[t] += add;
        __syncthreads();
    }
    if (t < NB1) g_bsum[t] = sm[t] - v;
    if (t == NB1 - 1) g_rowptr[NN] = sm[t];
}

__global__ void scan3_k() {
    int i = blockIdx.x * blockDim.x + threadIdx.x;
    if (i < NN) {
        int e = g_rowptr[i] + g_bsum[i >> 9];
        g_rowptr[i] = e;
        g_cursor[i] = e;
        int d = g_deg[i];
        g_invdeg[i] = 1.0f / (float)((d > 1) ? d : 1);
    }
}

__global__ void fill_csr_k(const int* __restrict__ src, const int* __restrict__ dst) {
    int e = blockIdx.x * blockDim.x + threadIdx.x;
    if (e < NE) {
        int d = dst[e];
        int p = atomicAdd(&g_cursor[d], 1);
        g_col[p] = src[e];
    }
}

// ---------------- aggregation (fp16 gather, fp32 accumulate) -----------------
__device__ __forceinline__ void acc8(float* s, uint4 v) {
    __half2 a = *reinterpret_cast<__half2*>(&v.x);
    __half2 b = *reinterpret_cast<__half2*>(&v.y);
    __half2 c = *reinterpret_cast<__half2*>(&v.z);
    __half2 d = *reinterpret_cast<__half2*>(&v.w);
    float2 fa = __half22float2(a), fb = __half22float2(b);
    float2 fc = __half22float2(c), fd = __half22float2(d);
    s[0] += fa.x; s[1] += fa.y; s[2] += fb.x; s[3] += fb.y;
    s[4] += fc.x; s[5] += fc.y; s[6] += fd.x; s[7] += fd.y;
}

__global__ void aggregate_h_k(const __half* __restrict__ h) {
    int node = (int)((blockIdx.x * blockDim.x + threadIdx.x) >> 5);
    if (node >= NN) return;
    int lane = threadIdx.x & 31;
    int beg = g_rowptr[node], end = g_rowptr[node + 1];
    float s[8];
    #pragma unroll
    for (int q = 0; q < 8; ++q) s[q] = 0.f;
    int e = beg;
    for (; e + 3 < end; e += 4) {
        int i0 = g_col[e], i1 = g_col[e + 1], i2 = g_col[e + 2], i3 = g_col[e + 3];
        uint4 v0 = __ldg(reinterpret_cast<const uint4*>(h + (size_t)i0 * DIM) + lane);
        uint4 v1 = __ldg(reinterpret_cast<const uint4*>(h + (size_t)i1 * DIM) + lane);
        uint4 v2 = __ldg(reinterpret_cast<const uint4*>(h + (size_t)i2 * DIM) + lane);
        uint4 v3 = __ldg(reinterpret_cast<const uint4*>(h + (size_t)i3 * DIM) + lane);
        acc8(s, v0); acc8(s, v1); acc8(s, v2); acc8(s, v3);
    }
    for (; e < end; ++e) {
        int i0 = g_col[e];
        uint4 v0 = __ldg(reinterpret_cast<const uint4*>(h + (size_t)i0 * DIM) + lane);
        acc8(s, v0);
    }
    float inv = g_invdeg[node];
    __half2 o0 = __floats2half2_rn(s[0] * inv, s[1] * inv);
    __half2 o1 = __floats2half2_rn(s[2] * inv, s[3] * inv);
    __half2 o2 = __floats2half2_rn(s[4] * inv, s[5] * inv);
    __half2 o3 = __floats2half2_rn(s[6] * inv, s[7] * inv);
    uint4 pk;
    pk.x = *reinterpret_cast<unsigned*>(&o0);
    pk.y = *reinterpret_cast<unsigned*>(&o1);
    pk.z = *reinterpret_cast<unsigned*>(&o2);
    pk.w = *reinterpret_cast<unsigned*>(&o3);
    *(reinterpret_cast<uint4*>(g_meanh + (size_t)node * DIM) + lane) = pk;
}

// ---------------- fp16 tensor-core GEMM primitives ----------------------------
__device__ __forceinline__ uint32_t smem_u32(const void* p) {
    uint32_t a;
    asm("{ .reg .u64 t; cvta.to.shared.u64 t, %1; cvt.u32.u64 %0, t; }"
        : "=r"(a) : "l"(p));
    return a;
}

__device__ __forceinline__ void mma_f16(float* d, const unsigned* a, const unsigned* b) {
    asm volatile(
        "mma.sync.aligned.m16n8k16.row.col.f32.f16.f16.f32 "
        "{%0,%1,%2,%3}, {%4,%5,%6,%7}, {%8,%9}, {%0,%1,%2,%3};"
        : "+f"(d[0]), "+f"(d[1]), "+f"(d[2]), "+f"(d[3])
        : "r"(a[0]), "r"(a[1]), "r"(a[2]), "r"(a[3]),
          "r"(b[0]), "r"(b[1]));
}

__device__ __forceinline__ void ldsm_x4(unsigned& r0, unsigned& r1,
                                        unsigned& r2, unsigned& r3, uint32_t addr) {
    asm volatile("ldmatrix.sync.aligned.m8n8.x4.shared.b16 {%0,%1,%2,%3}, [%4];"
                 : "=r"(r0), "=r"(r1), "=r"(r2), "=r"(r3) : "r"(addr));
}

#define SA 24

// ---- wide GEMM for layers 0/1: BM=128, BN=256, 512 threads (16 warps 4x4) ---
// C = relu(A0@W0^T + A1@W1^T + bias), all Nout=256, fp16 out.
__global__ __launch_bounds__(512) void gemm_wide_k(
    const __half* __restrict__ A0, const __half* __restrict__ A1,
    const __half* __restrict__ W0, const __half* __restrict__ W1,
    const float* __restrict__ bias, __half* __restrict__ Ch)
{
    __shared__ __align__(16) __half As[2][128 * SA];
    __shared__ __align__(16) __half Ws[2][256 * SA];
    int tid = threadIdx.x;
    int lane = tid & 31, wid = tid >> 5;
    int wr = wid >> 2, wc = wid & 3;       // 4x4 warp grid
    int i0 = blockIdx.x * 128;

    // A: threads 0..255 load 128 rows x 2 chunks; W: all 512 load 256 rows x 2
    const bool aload = (tid < 256);
    int arow = (tid & 255) >> 1, akb = (tid & 1) << 3;
    int gi = i0 + arow; if (gi >= NN) gi = NN - 1;
    int wrow = tid >> 1;                   // 0..255
    int wkb = (tid & 1) << 3;

    float acc[2][8][4];
    #pragma unroll
    for (int mi = 0; mi < 2; ++mi)
        #pragma unroll
        for (int ni = 0; ni < 8; ++ni)
            #pragma unroll
            for (int q = 0; q < 4; ++q) acc[mi][ni][q] = 0.f;

    const int lrow = lane & 15;
    const int lcol = (lane >> 4) << 3;
    const uint32_t a_sm0 = smem_u32(&As[0][0]);
    const uint32_t w_sm0 = smem_u32(&Ws[0][0]);
    const uint32_t abufstride = 128 * SA * 2;
    const uint32_t wbufstride = 256 * SA * 2;
    const int r4 = lane >> 2, c4 = lane & 3;

    #pragma unroll
    for (int p = 0; p < 2; ++p) {
        const __half* Ap = p ? A1 : A0;
        const __half* Wp = p ? W1 : W0;

        // prologue: k-tile 0 -> buf 0
        {
            if (aload) {
                uint4 ra = *reinterpret_cast<const uint4*>(Ap + (size_t)gi * DIM + akb);
                *reinterpret_cast<uint4*>(&As[0][arow * SA + akb]) = ra;
            }
            uint4 rw = *reinterpret_cast<const uint4*>(Wp + (size_t)wrow * DIM + wkb);
            *reinterpret_cast<uint4*>(&Ws[0][wrow * SA + wkb]) = rw;
        }
        __syncthreads();

        int buf = 0;
        for (int k0 = 16; k0 <= DIM; k0 += 16) {
            uint4 na, nw;
            bool have_next = (k0 < DIM);
            if (have_next) {
                if (aload)
                    na = *reinterpret_cast<const uint4*>(Ap + (size_t)gi * DIM + k0 + akb);
                nw = *reinterpret_cast<const uint4*>(Wp + (size_t)wrow * DIM + k0 + wkb);
            }

            uint32_t a_sm = a_sm0 + buf * abufstride;
            uint32_t w_sm = w_sm0 + buf * wbufstride;
            unsigned afr[2][4];
            #pragma unroll
            for (int mi = 0; mi < 2; ++mi) {
                uint32_t addr = a_sm + (uint32_t)(((wr * 32 + mi * 16 + lrow) * SA + lcol) * 2);
                ldsm_x4(afr[mi][0], afr[mi][1], afr[mi][2], afr[mi][3], addr);
            }
            unsigned bfr[8][2];
            #pragma unroll
            for (int p4 = 0; p4 < 4; ++p4) {
                uint32_t addr = w_sm + (uint32_t)(((wc * 64 + p4 * 16 + lrow) * SA + lcol) * 2);
                ldsm_x4(bfr[2 * p4][0], bfr[2 * p4 + 1][0],
                        bfr[2 * p4][1], bfr[2 * p4 + 1][1], addr);
            }
            #pragma unroll
            for (int mi = 0; mi < 2; ++mi)
                #pragma unroll
                for (int ni = 0; ni < 8; ++ni)
                    mma_f16(acc[mi][ni], afr[mi], bfr[ni]);

            if (have_next) {
                int nb = buf ^ 1;
                if (aload)
                    *reinterpret_cast<uint4*>(&As[nb][arow * SA + akb]) = na;
                *reinterpret_cast<uint4*>(&Ws[nb][wrow * SA + wkb]) = nw;
                __syncthreads();
                buf = nb;
            }
        }
        __syncthreads();
    }

    // epilogue: bias + relu + fp16 pack, Nout=256
    #pragma unroll
    for (int mi = 0; mi < 2; ++mi) {
        #pragma unroll
        for (int half = 0; half < 2; ++half) {
            int grow = i0 + wr * 32 + mi * 16 + r4 + half * 8;
            if (grow >= NN) continue;
            #pragma unroll
            for (int ni = 0; ni < 8; ++ni) {
                int gcol = wc * 64 + ni * 8 + c4 * 2;
                float v0 = acc[mi][ni][half * 2 + 0] + bias[gcol];
                float v1 = acc[mi][ni][half * 2 + 1] + bias[gcol + 1];
                v0 = fmaxf(v0, 0.f); v1 = fmaxf(v1, 0.f);
                __half2 hv = __floats2half2_rn(v0, v1);
                *reinterpret_cast<__half2*>(Ch + (size_t)grow * 256 + gcol) = hv;
            }
        }
    }
}

// ---- 256-thread GEMM kept for the z projection (Nout=80) --------------------
template<bool RELU, bool HALF_OUT>
__global__ __launch_bounds__(256) void gemm_f16_k(
    const __half* __restrict__ A0, const __half* __restrict__ A1,
    const __half* __restrict__ W0, const __half* __restrict__ W1,
    const float* __restrict__ bias,
    __half* __restrict__ Ch, float* __restrict__ Cf,
    int Nout, int nphase)
{
    __shared__ __align__(16) __half As[2][128 * SA];
    __shared__ __align__(16) __half Ws[2][128 * SA];
    int tid = threadIdx.x;
    int lane = tid & 31, wid = tid >> 5;
    int wr = wid >> 1, wc = wid & 1;
    int i0 = blockIdx.x * 128, j0 = blockIdx.y * 128;

    int arow = tid >> 1, akb = (tid & 1) << 3;
    int gi = i0 + arow; if (gi >= NN) gi = NN - 1;
    const bool w_ok = (j0 + arow < Nout);

    float acc[2][8][4];
    #pragma unroll
    for (int mi = 0; mi < 2; ++mi)
        #pragma unroll
        for (int ni = 0; ni < 8; ++ni)
            #pragma unroll
            for (int q = 0; q < 4; ++q) acc[mi][ni][q] = 0.f;

    const int lrow = lane & 15;
    const int lcol = (lane >> 4) << 3;
    const uint32_t a_sm0 = smem_u32(&As[0][0]);
    const uint32_t w_sm0 = smem_u32(&Ws[0][0]);
    const uint32_t bufstride = 128 * SA * 2;
    const int r4 = lane >> 2, c4 = lane & 3;

    for (int p = 0; p < nphase; ++p) {
        const __half* Ap = p ? A1 : A0;
        const __half* Wp = p ? W1 : W0;

        {
            uint4 ra = *reinterpret_cast<const uint4*>(Ap + (size_t)gi * DIM + akb);
            uint4 rw = make_uint4(0, 0, 0, 0);
            if (w_ok) rw = *reinterpret_cast<const uint4*>(Wp + (size_t)(j0 + arow) * DIM + akb);
            *reinterpret_cast<uint4*>(&As[0][arow * SA + akb]) = ra;
            *reinterpret_cast<uint4*>(&Ws[0][arow * SA + akb]) = rw;
        }
        __syncthreads();

        int buf = 0;
        for (int k0 = 16; k0 <= DIM; k0 += 16) {
            uint4 na, nw;
            bool have_next = (k0 < DIM);
            if (have_next) {
                na = *reinterpret_cast<const uint4*>(Ap + (size_t)gi * DIM + k0 + akb);
                nw = make_uint4(0, 0, 0, 0);
                if (w_ok) nw = *reinterpret_cast<const uint4*>(Wp + (size_t)(j0 + arow) * DIM + k0 + akb);
            }

            uint32_t a_sm = a_sm0 + buf * bufstride;
            uint32_t w_sm = w_sm0 + buf * bufstride;
            unsigned afr[2][4];
            #pragma unroll
            for (int mi = 0; mi < 2; ++mi) {
                uint32_t addr = a_sm + (uint32_t)(((wr * 32 + mi * 16 + lrow) * SA + lcol) * 2);
                ldsm_x4(afr[mi][0], afr[mi][1], afr[mi][2], afr[mi][3], addr);
            }
            unsigned bfr[8][2];
            #pragma unroll
            for (int p4 = 0; p4 < 4; ++p4) {
                uint32_t addr = w_sm + (uint32_t)(((wc * 64 + p4 * 16 + lrow) * SA + lcol) * 2);
                ldsm_x4(bfr[2 * p4][0], bfr[2 * p4 + 1][0],
                        bfr[2 * p4][1], bfr[2 * p4 + 1][1], addr);
            }
            #pragma unroll
            for (int mi = 0; mi < 2; ++mi)
                #pragma unroll
                for (int ni = 0; ni < 8; ++ni)
                    mma_f16(acc[mi][ni], afr[mi], bfr[ni]);

            if (have_next) {
                int nb = buf ^ 1;
                *reinterpret_cast<uint4*>(&As[nb][arow * SA + akb]) = na;
                *reinterpret_cast<uint4*>(&Ws[nb][arow * SA + akb]) = nw;
                __syncthreads();
                buf = nb;
            }
        }
        __syncthreads();
    }

    #pragma unroll
    for (int mi = 0; mi < 2; ++mi) {
        #pragma unroll
        for (int half = 0; half < 2; ++half) {
            int grow = i0 + wr * 32 + mi * 16 + r4 + half * 8;
            if (grow >= NN) continue;
            #pragma unroll
            for (int ni = 0; ni < 8; ++ni) {
                int gcol = j0 + wc * 64 + ni * 8 + c4 * 2;
                if (gcol >= Nout) continue;
                float v0 = acc[mi][ni][half * 2 + 0] + (bias ? bias[gcol] : 0.f);
                float v1 = acc[mi][ni][half * 2 + 1] + (bias ? bias[gcol + 1] : 0.f);
                if (RELU) { v0 = fmaxf(v0, 0.f); v1 = fmaxf(v1, 0.f); }
                if (HALF_OUT) {
                    __half2 hv = __floats2half2_rn(v0, v1);
                    *reinterpret_cast<__half2*>(Ch + (size_t)grow * Nout + gcol) = hv;
                } else {
                    *reinterpret_cast<float2*>(Cf + (size_t)grow * Nout + gcol) =
                        make_float2(v0, v1);
                }
            }
        }
    }
}

// ------- layer-2 tail: fp16 gather (80B/edge) + bias + log_softmax -----------
__global__ void agg40h_lsm_k(const float* __restrict__ b2, float* __restrict__ out) {
    int node = (int)((blockIdx.x * blockDim.x + threadIdx.x) >> 5);
    if (node >= NN) return;
    int lane = threadIdx.x & 31;
    bool act = (lane < 5);
    int beg = g_rowptr[node], end = g_rowptr[node + 1];
    float s[8];
    #pragma unroll
    for (int q = 0; q < 8; ++q) s[q] = 0.f;
    int e = beg;
    for (; e + 3 < end; e += 4) {
        int i0 = g_col[e], i1 = g_col[e + 1], i2 = g_col[e + 2], i3 = g_col[e + 3];
        if (act) {
            uint4 v0 = __ldg(reinterpret_cast<const uint4*>(g_zh + (size_t)i0 * 80) + lane);
            uint4 v1 = __ldg(reinterpret_cast<const uint4*>(g_zh + (size_t)i1 * 80) + lane);
            uint4 v2 = __ldg(reinterpret_cast<const uint4*>(g_zh + (size_t)i2 * 80) + lane);
            uint4 v3 = __ldg(reinterpret_cast<const uint4*>(g_zh + (size_t)i3 * 80) + lane);
            acc8(s, v0); acc8(s, v1); acc8(s, v2); acc8(s, v3);
        }
    }
    for (; e < end; ++e) {
        int i0 = g_col[e];
        if (act) {
            uint4 v0 = __ldg(reinterpret_cast<const uint4*>(g_zh + (size_t)i0 * 80) + lane);
            acc8(s, v0);
        }
    }
    float v[8];
    float mymax = -INFINITY;
    if (act) {
        float inv = g_invdeg[node];
        float rf[8];
        #pragma unroll
        for (int q = 0; q < 8; ++q) rf[q] = 0.f;
        uint4 rv = __ldg(reinterpret_cast<const uint4*>(g_zh + (size_t)node * 80 + 40) + lane);
        acc8(rf, rv);
        float4 bb0 = *reinterpret_cast<const float4*>(b2 + 8 * lane);
        float4 bb1 = *reinterpret_cast<const float4*>(b2 + 8 * lane + 4);
        float bb[8] = {bb0.x, bb0.y, bb0.z, bb0.w, bb1.x, bb1.y, bb1.z, bb1.w};
        #pragma unroll
        for (int q = 0; q < 8; ++q) {
            v[q] = s[q] * inv + rf[q] + bb[q];
            mymax = fmaxf(mymax, v[q]);
        }
    }
    #pragma unroll
    for (int off = 16; off > 0; off >>= 1)
        mymax = fmaxf(mymax, __shfl_xor_sync(0xffffffffu, mymax, off));
    float se = 0.f;
    if (act) {
        #pragma unroll
        for (int q = 0; q < 8; ++q) se += expf(v[q] - mymax);
    }
    #pragma unroll
    for (int off = 16; off > 0; off >>= 1)
        se += __shfl_xor_sync(0xffffffffu, se, off);
    float ls = mymax + logf(se);
    if (act) {
        float4 o0 = make_float4(v[0] - ls, v[1] - ls, v[2] - ls, v[3] - ls);
        float4 o1 = make_float4(v[4] - ls, v[5] - ls, v[6] - ls, v[7] - ls);
        float* po = out + (size_t)node * DOUT + 8 * lane;
        *reinterpret_cast<float4*>(po) = o0;
        *reinterpret_cast<float4*>(po + 4) = o1;
    }
}

// ---------------- launch -----------------------------------------------------
extern "C" void kernel_launch(void* const* d_in, const int* in_sizes, int n_in,
                              void* d_out, int out_size) {
    const float* x   = (const float*)d_in[0];
    const int*   ei  = (const int*)d_in[1];
    const int*   src = ei;
    const int*   dst = ei + NE;
    const float* Wl0 = (const float*)d_in[2];
    const float* Wr0 = (const float*)d_in[3];
    const float* b0  = (const float*)d_in[4];
    const float* Wl1 = (const float*)d_in[5];
    const float* Wr1 = (const float*)d_in[6];
    const float* b1  = (const float*)d_in[7];
    const float* Wl2 = (const float*)d_in[8];
    const float* Wr2 = (const float*)d_in[9];
    const float* b2  = (const float*)d_in[10];
    float* out = (float*)d_out;

    __half *p_xh, *p_meanh, *p_h0h, *p_h1h, *p_zh;
    __half *p_Wl0h, *p_Wr0h, *p_Wl1h, *p_Wr1h, *p_W2h;
    cudaGetSymbolAddress((void**)&p_xh, g_xh);
    cudaGetSymbolAddress((void**)&p_meanh, g_meanh);
    cudaGetSymbolAddress((void**)&p_h0h, g_h0h);
    cudaGetSymbolAddress((void**)&p_h1h, g_h1h);
    cudaGetSymbolAddress((void**)&p_zh, g_zh);
    cudaGetSymbolAddress((void**)&p_Wl0h, g_Wl0h);
    cudaGetSymbolAddress((void**)&p_Wr0h, g_Wr0h);
    cudaGetSymbolAddress((void**)&p_Wl1h, g_Wl1h);
    cudaGetSymbolAddress((void**)&p_Wr1h, g_Wr1h);
    cudaGetSymbolAddress((void**)&p_W2h, g_W2h);

    static cudaStream_t s2 = nullptr;
    static cudaEvent_t evFork, evCSR;
    if (!s2) {
        cudaStreamCreateWithFlags(&s2, cudaStreamNonBlocking);
        cudaEventCreateWithFlags(&evFork, cudaEventDisableTiming);
        cudaEventCreateWithFlags(&evCSR, cudaEventDisableTiming);
    }

    int gemmBlocks = (NN + 127) / 128;  // 782
    dim3 gz(gemmBlocks, 1);             // Nout=80
    int aggBlocks = (NN * 32 + 255) / 256;

    // ---- fork: CSR chain on stream B || prep on capture stream --------------
    cudaEventRecord(evFork, 0);
    cudaStreamWaitEvent(s2, evFork, 0);

    zero_deg_k<<<(NN + 255) / 256, 256, 0, s2>>>();
    count_deg_k<<<(NE + 255) / 256, 256, 0, s2>>>(dst);
    scan1_k<<<NB1, 512, 0, s2>>>();
    scan2_k<<<1, 256, 0, s2>>>();
    scan3_k<<<(NN + 255) / 256, 256, 0, s2>>>();
    fill_csr_k<<<(NE + 255) / 256, 256, 0, s2>>>(src, dst);
    cudaEventRecord(evCSR, s2);

    prep_k<<<(PREP_TOTAL + 255) / 256, 256>>>(x, Wl0, Wr0, Wl1, Wr1, Wl2, Wr2);

    // ---- join ----------------------------------------------------------------
    cudaStreamWaitEvent(0, evCSR, 0);

    // layer 0
    aggregate_h_k<<<aggBlocks, 256>>>(p_xh);
    gemm_wide_k<<<gemmBlocks, 512>>>(p_meanh, p_xh, p_Wl0h, p_Wr0h, b0, p_h0h);
    // layer 1
    aggregate_h_k<<<aggBlocks, 256>>>(p_h0h);
    gemm_wide_k<<<gemmBlocks, 512>>>(p_meanh, p_h0h, p_Wl1h, p_Wr1h, b1, p_h1h);
    // layer 2: project to 80-dim fp16 first (linearity), then aggregate + softmax
    gemm_f16_k<false, true><<<gz, 256>>>(p_h1h, nullptr, p_W2h, nullptr, nullptr,
                                         p_zh, nullptr, 80, 1);
    agg40h_lsm_k<<<aggBlocks, 256>>>(b2, out);
}

// round 15
// speedup vs baseline: 1.3164x; 1.0684x over previous
#include <cuda_runtime.h>
#include <cuda_fp16.h>
#include <math.h>
#include <stdint.h>

#define NN   100000
#define NE   1600000
#define DIM  256
#define DOUT 40

// ---------------- scratch (static device globals; no runtime alloc) ----------
__device__ int    g_deg[NN];
__device__ int    g_cursor[NN];
__device__ int    g_rowptr[NN + 1];
__device__ int    g_col[NE];
__device__ int    g_bsum[256];
__device__ float  g_invdeg[NN];
__device__ __half g_xh[(size_t)NN * DIM];
__device__ __half g_meanh[(size_t)NN * DIM];
__device__ __half g_h0h[(size_t)NN * DIM];
__device__ __half g_h1h[(size_t)NN * DIM];
__device__ __half g_zh[(size_t)NN * 80];       // layer-2 projected [yl(40)|yr(40)] fp16
__device__ __half g_Wl0h[DIM * DIM];           // transposed [n][k] fp16
__device__ __half g_Wr0h[DIM * DIM];
__device__ __half g_Wl1h[DIM * DIM];
__device__ __half g_Wr1h[DIM * DIM];
__device__ __half g_W2h[80 * DIM];             // [n(80)][k(256)]

// ---------------- prep: conv_x + all weight packs ----------------------------
#define PREP_TOTAL 6682624
__global__ void prep_k(const float* __restrict__ x,
                       const float* __restrict__ Wl0, const float* __restrict__ Wr0,
                       const float* __restrict__ Wl1, const float* __restrict__ Wr1,
                       const float* __restrict__ Wl2, const float* __restrict__ Wr2) {
    int i = blockIdx.x * blockDim.x + threadIdx.x;
    if (i < 6400000) {
        float4 v = *reinterpret_cast<const float4*>(x + (size_t)i * 4);
        __half2 h0 = __floats2half2_rn(v.x, v.y);
        __half2 h1 = __floats2half2_rn(v.z, v.w);
        uint2 pk;
        pk.x = *reinterpret_cast<unsigned*>(&h0);
        pk.y = *reinterpret_cast<unsigned*>(&h1);
        *reinterpret_cast<uint2*>(g_xh + (size_t)i * 4) = pk;
    } else if (i < 6662144) {
        int j = i - 6400000;
        int w = j >> 16;
        int r = j & 65535;
        const float* W = (w == 0) ? Wl0 : (w == 1) ? Wr0 : (w == 2) ? Wl1 : Wr1;
        __half* o = (w == 0) ? g_Wl0h : (w == 1) ? g_Wr0h : (w == 2) ? g_Wl1h : g_Wr1h;
        int n = r >> 8, k = r & 255;
        o[(size_t)n * DIM + k] = __float2half_rn(W[(size_t)k * DIM + n]);
    } else if (i < PREP_TOTAL) {
        int j = i - 6662144;
        int w = j / 10240, r = j % 10240;
        const float* W = w ? Wr2 : Wl2;
        int n = r >> 8, k = r & 255;
        g_W2h[(size_t)(w * 40 + n) * DIM + k] = __float2half_rn(W[(size_t)k * DOUT + n]);
    }
}

// ---------------- CSR build --------------------------------------------------
__global__ void zero_deg_k() {
    int i = blockIdx.x * blockDim.x + threadIdx.x;
    if (i < NN) g_deg[i] = 0;
}

__global__ void count_deg_k(const int* __restrict__ dst) {
    int e = blockIdx.x * blockDim.x + threadIdx.x;
    if (e < NE) atomicAdd(&g_deg[dst[e]], 1);
}

#define NB1 196   // ceil(NN / 512)
__global__ void scan1_k() {
    __shared__ int wsum[16];
    int tid = threadIdx.x, lane = tid & 31, wid = tid >> 5;
    int i = blockIdx.x * 512 + tid;
    int v = (i < NN) ? g_deg[i] : 0;
    int x = v;
    #pragma unroll
    for (int off = 1; off < 32; off <<= 1) {
        int t = __shfl_up_sync(0xffffffffu, x, off);
        if (lane >= off) x += t;
    }
    if (lane == 31) wsum[wid] = x;
    __syncthreads();
    if (wid == 0 && lane < 16) {
        int w = wsum[lane];
        #pragma unroll
        for (int off = 1; off < 16; off <<= 1) {
            int t = __shfl_up_sync(0x0000ffffu, w, off);
            if (lane >= off) w += t;
        }
        wsum[lane] = w;
    }
    __syncthreads();
    int excl = x - v + ((wid > 0) ? wsum[wid - 1] : 0);
    if (i < NN) g_rowptr[i] = excl;
    if (tid == 0) g_bsum[blockIdx.x] = wsum[15];
}

__global__ void scan2_k() {
    __shared__ int sm[256];
    int t = threadIdx.x;
    int v = (t < NB1) ? g_bsum[t] : 0;
    sm[t] = v;
    __syncthreads();
    #pragma unroll
    for (int off = 1; off < 256; off <<= 1) {
        int add = (t >= off) ? sm[t - off] : 0;
        __syncthreads();
        sm[t] += add;
        __syncthreads();
    }
    if (t < NB1) g_bsum[t] = sm[t] - v;
    if (t == NB1 - 1) g_rowptr[NN] = sm[t];
}

__global__ void scan3_k() {
    int i = blockIdx.x * blockDim.x + threadIdx.x;
    if (i < NN) {
        int e = g_rowptr[i] + g_bsum[i >> 9];
        g_rowptr[i] = e;
        g_cursor[i] = e;
        int d = g_deg[i];
        g_invdeg[i] = 1.0f / (float)((d > 1) ? d : 1);
    }
}

__global__ void fill_csr_k(const int* __restrict__ src, const int* __restrict__ dst) {
    int e = blockIdx.x * blockDim.x + threadIdx.x;
    if (e < NE) {
        int d = dst[e];
        int p = atomicAdd(&g_cursor[d], 1);
        g_col[p] = src[e];
    }
}

// ---------------- aggregation (fp16 gather, fp32 accumulate) -----------------
__device__ __forceinline__ void acc8(float* s, uint4 v) {
    __half2 a = *reinterpret_cast<__half2*>(&v.x);
    __half2 b = *reinterpret_cast<__half2*>(&v.y);
    __half2 c = *reinterpret_cast<__half2*>(&v.z);
    __half2 d = *reinterpret_cast<__half2*>(&v.w);
    float2 fa = __half22float2(a), fb = __half22float2(b);
    float2 fc = __half22float2(c), fd = __half22float2(d);
    s[0] += fa.x; s[1] += fa.y; s[2] += fb.x; s[3] += fb.y;
    s[4] += fc.x; s[5] += fc.y; s[6] += fd.x; s[7] += fd.y;
}

__global__ void aggregate_h_k(const __half* __restrict__ h) {
    int node = (int)((blockIdx.x * blockDim.x + threadIdx.x) >> 5);
    if (node >= NN) return;
    int lane = threadIdx.x & 31;
    int beg = g_rowptr[node], end = g_rowptr[node + 1];
    float s[8];
    #pragma unroll
    for (int q = 0; q < 8; ++q) s[q] = 0.f;
    int e = beg;
    for (; e + 3 < end; e += 4) {
        int i0 = g_col[e], i1 = g_col[e + 1], i2 = g_col[e + 2], i3 = g_col[e + 3];
        uint4 v0 = __ldg(reinterpret_cast<const uint4*>(h + (size_t)i0 * DIM) + lane);
        uint4 v1 = __ldg(reinterpret_cast<const uint4*>(h + (size_t)i1 * DIM) + lane);
        uint4 v2 = __ldg(reinterpret_cast<const uint4*>(h + (size_t)i2 * DIM) + lane);
        uint4 v3 = __ldg(reinterpret_cast<const uint4*>(h + (size_t)i3 * DIM) + lane);
        acc8(s, v0); acc8(s, v1); acc8(s, v2); acc8(s, v3);
    }
    for (; e < end; ++e) {
        int i0 = g_col[e];
        uint4 v0 = __ldg(reinterpret_cast<const uint4*>(h + (size_t)i0 * DIM) + lane);
        acc8(s, v0);
    }
    float inv = g_invdeg[node];
    __half2 o0 = __floats2half2_rn(s[0] * inv, s[1] * inv);
    __half2 o1 = __floats2half2_rn(s[2] * inv, s[3] * inv);
    __half2 o2 = __floats2half2_rn(s[4] * inv, s[5] * inv);
    __half2 o3 = __floats2half2_rn(s[6] * inv, s[7] * inv);
    uint4 pk;
    pk.x = *reinterpret_cast<unsigned*>(&o0);
    pk.y = *reinterpret_cast<unsigned*>(&o1);
    pk.z = *reinterpret_cast<unsigned*>(&o2);
    pk.w = *reinterpret_cast<unsigned*>(&o3);
    *(reinterpret_cast<uint4*>(g_meanh + (size_t)node * DIM) + lane) = pk;
}

// ---------------- fp16 tensor-core GEMM primitives ----------------------------
__device__ __forceinline__ uint32_t smem_u32(const void* p) {
    uint32_t a;
    asm("{ .reg .u64 t; cvta.to.shared.u64 t, %1; cvt.u32.u64 %0, t; }"
        : "=r"(a) : "l"(p));
    return a;
}

__device__ __forceinline__ void mma_f16(float* d, const unsigned* a, const unsigned* b) {
    asm volatile(
        "mma.sync.aligned.m16n8k16.row.col.f32.f16.f16.f32 "
        "{%0,%1,%2,%3}, {%4,%5,%6,%7}, {%8,%9}, {%0,%1,%2,%3};"
        : "+f"(d[0]), "+f"(d[1]), "+f"(d[2]), "+f"(d[3])
        : "r"(a[0]), "r"(a[1]), "r"(a[2]), "r"(a[3]),
          "r"(b[0]), "r"(b[1]));
}

__device__ __forceinline__ void ldsm_x4(unsigned& r0, unsigned& r1,
                                        unsigned& r2, unsigned& r3, uint32_t addr) {
    asm volatile("ldmatrix.sync.aligned.m8n8.x4.shared.b16 {%0,%1,%2,%3}, [%4];"
                 : "=r"(r0), "=r"(r1), "=r"(r2), "=r"(r3) : "r"(addr));
}

#define SA 24

// ---- wide GEMM for layers 0/1: BM=128, BN=256, 512 threads (16 warps 4x4) ---
__global__ __launch_bounds__(512) void gemm_wide_k(
    const __half* __restrict__ A0, const __half* __restrict__ A1,
    const __half* __restrict__ W0, const __half* __restrict__ W1,
    const float* __restrict__ bias, __half* __restrict__ Ch)
{
    __shared__ __align__(16) __half As[2][128 * SA];
    __shared__ __align__(16) __half Ws[2][256 * SA];
    int tid = threadIdx.x;
    int lane = tid & 31, wid = tid >> 5;
    int wr = wid >> 2, wc = wid & 3;       // 4x4 warp grid
    int i0 = blockIdx.x * 128;

    const bool aload = (tid < 256);
    int arow = (tid & 255) >> 1, akb = (tid & 1) << 3;
    int gi = i0 + arow; if (gi >= NN) gi = NN - 1;
    int wrow = tid >> 1;
    int wkb = (tid & 1) << 3;

    float acc[2][8][4];
    #pragma unroll
    for (int mi = 0; mi < 2; ++mi)
        #pragma unroll
        for (int ni = 0; ni < 8; ++ni)
            #pragma unroll
            for (int q = 0; q < 4; ++q) acc[mi][ni][q] = 0.f;

    const int lrow = lane & 15;
    const int lcol = (lane >> 4) << 3;
    const uint32_t a_sm0 = smem_u32(&As[0][0]);
    const uint32_t w_sm0 = smem_u32(&Ws[0][0]);
    const uint32_t abufstride = 128 * SA * 2;
    const uint32_t wbufstride = 256 * SA * 2;
    const int r4 = lane >> 2, c4 = lane & 3;

    #pragma unroll
    for (int p = 0; p < 2; ++p) {
        const __half* Ap = p ? A1 : A0;
        const __half* Wp = p ? W1 : W0;

        {
            if (aload) {
                uint4 ra = *reinterpret_cast<const uint4*>(Ap + (size_t)gi * DIM + akb);
                *reinterpret_cast<uint4*>(&As[0][arow * SA + akb]) = ra;
            }
            uint4 rw = *reinterpret_cast<const uint4*>(Wp + (size_t)wrow * DIM + wkb);
            *reinterpret_cast<uint4*>(&Ws[0][wrow * SA + wkb]) = rw;
        }
        __syncthreads();

        int buf = 0;
        for (int k0 = 16; k0 <= DIM; k0 += 16) {
            uint4 na, nw;
            bool have_next = (k0 < DIM);
            if (have_next) {
                if (aload)
                    na = *reinterpret_cast<const uint4*>(Ap + (size_t)gi * DIM + k0 + akb);
                nw = *reinterpret_cast<const uint4*>(Wp + (size_t)wrow * DIM + k0 + wkb);
            }

            uint32_t a_sm = a_sm0 + buf * abufstride;
            uint32_t w_sm = w_sm0 + buf * wbufstride;
            unsigned afr[2][4];
            #pragma unroll
            for (int mi = 0; mi < 2; ++mi) {
                uint32_t addr = a_sm + (uint32_t)(((wr * 32 + mi * 16 + lrow) * SA + lcol) * 2);
                ldsm_x4(afr[mi][0], afr[mi][1], afr[mi][2], afr[mi][3], addr);
            }
            unsigned bfr[8][2];
            #pragma unroll
            for (int p4 = 0; p4 < 4; ++p4) {
                uint32_t addr = w_sm + (uint32_t)(((wc * 64 + p4 * 16 + lrow) * SA + lcol) * 2);
                ldsm_x4(bfr[2 * p4][0], bfr[2 * p4 + 1][0],
                        bfr[2 * p4][1], bfr[2 * p4 + 1][1], addr);
            }
            #pragma unroll
            for (int mi = 0; mi < 2; ++mi)
                #pragma unroll
                for (int ni = 0; ni < 8; ++ni)
                    mma_f16(acc[mi][ni], afr[mi], bfr[ni]);

            if (have_next) {
                int nb = buf ^ 1;
                if (aload)
                    *reinterpret_cast<uint4*>(&As[nb][arow * SA + akb]) = na;
                *reinterpret_cast<uint4*>(&Ws[nb][wrow * SA + wkb]) = nw;
                __syncthreads();
                buf = nb;
            }
        }
        __syncthreads();
    }

    #pragma unroll
    for (int mi = 0; mi < 2; ++mi) {
        #pragma unroll
        for (int half = 0; half < 2; ++half) {
            int grow = i0 + wr * 32 + mi * 16 + r4 + half * 8;
            if (grow >= NN) continue;
            #pragma unroll
            for (int ni = 0; ni < 8; ++ni) {
                int gcol = wc * 64 + ni * 8 + c4 * 2;
                float v0 = acc[mi][ni][half * 2 + 0] + bias[gcol];
                float v1 = acc[mi][ni][half * 2 + 1] + bias[gcol + 1];
                v0 = fmaxf(v0, 0.f); v1 = fmaxf(v1, 0.f);
                __half2 hv = __floats2half2_rn(v0, v1);
                *reinterpret_cast<__half2*>(Ch + (size_t)grow * 256 + gcol) = hv;
            }
        }
    }
}

// ---- 256-thread GEMM kept for the z projection (Nout=80) --------------------
template<bool RELU, bool HALF_OUT>
__global__ __launch_bounds__(256) void gemm_f16_k(
    const __half* __restrict__ A0, const __half* __restrict__ A1,
    const __half* __restrict__ W0, const __half* __restrict__ W1,
    const float* __restrict__ bias,
    __half* __restrict__ Ch, float* __restrict__ Cf,
    int Nout, int nphase)
{
    __shared__ __align__(16) __half As[2][128 * SA];
    __shared__ __align__(16) __half Ws[2][128 * SA];
    int tid = threadIdx.x;
    int lane = tid & 31, wid = tid >> 5;
    int wr = wid >> 1, wc = wid & 1;
    int i0 = blockIdx.x * 128, j0 = blockIdx.y * 128;

    int arow = tid >> 1, akb = (tid & 1) << 3;
    int gi = i0 + arow; if (gi >= NN) gi = NN - 1;
    const bool w_ok = (j0 + arow < Nout);

    float acc[2][8][4];
    #pragma unroll
    for (int mi = 0; mi < 2; ++mi)
        #pragma unroll
        for (int ni = 0; ni < 8; ++ni)
            #pragma unroll
            for (int q = 0; q < 4; ++q) acc[mi][ni][q] = 0.f;

    const int lrow = lane & 15;
    const int lcol = (lane >> 4) << 3;
    const uint32_t a_sm0 = smem_u32(&As[0][0]);
    const uint32_t w_sm0 = smem_u32(&Ws[0][0]);
    const uint32_t bufstride = 128 * SA * 2;
    const int r4 = lane >> 2, c4 = lane & 3;

    for (int p = 0; p < nphase; ++p) {
        const __half* Ap = p ? A1 : A0;
        const __half* Wp = p ? W1 : W0;

        {
            uint4 ra = *reinterpret_cast<const uint4*>(Ap + (size_t)gi * DIM + akb);
            uint4 rw = make_uint4(0, 0, 0, 0);
            if (w_ok) rw = *reinterpret_cast<const uint4*>(Wp + (size_t)(j0 + arow) * DIM + akb);
            *reinterpret_cast<uint4*>(&As[0][arow * SA + akb]) = ra;
            *reinterpret_cast<uint4*>(&Ws[0][arow * SA + akb]) = rw;
        }
        __syncthreads();

        int buf = 0;
        for (int k0 = 16; k0 <= DIM; k0 += 16) {
            uint4 na, nw;
            bool have_next = (k0 < DIM);
            if (have_next) {
                na = *reinterpret_cast<const uint4*>(Ap + (size_t)gi * DIM + k0 + akb);
                nw = make_uint4(0, 0, 0, 0);
                if (w_ok) nw = *reinterpret_cast<const uint4*>(Wp + (size_t)(j0 + arow) * DIM + k0 + akb);
            }

            uint32_t a_sm = a_sm0 + buf * bufstride;
            uint32_t w_sm = w_sm0 + buf * bufstride;
            unsigned afr[2][4];
            #pragma unroll
            for (int mi = 0; mi < 2; ++mi) {
                uint32_t addr = a_sm + (uint32_t)(((wr * 32 + mi * 16 + lrow) * SA + lcol) * 2);
                ldsm_x4(afr[mi][0], afr[mi][1], afr[mi][2], afr[mi][3], addr);
            }
            unsigned bfr[8][2];
            #pragma unroll
            for (int p4 = 0; p4 < 4; ++p4) {
                uint32_t addr = w_sm + (uint32_t)(((wc * 64 + p4 * 16 + lrow) * SA + lcol) * 2);
                ldsm_x4(bfr[2 * p4][0], bfr[2 * p4 + 1][0],
                        bfr[2 * p4][1], bfr[2 * p4 + 1][1], addr);
            }
            #pragma unroll
            for (int mi = 0; mi < 2; ++mi)
                #pragma unroll
                for (int ni = 0; ni < 8; ++ni)
                    mma_f16(acc[mi][ni], afr[mi], bfr[ni]);

            if (have_next) {
                int nb = buf ^ 1;
                *reinterpret_cast<uint4*>(&As[nb][arow * SA + akb]) = na;
                *reinterpret_cast<uint4*>(&Ws[nb][arow * SA + akb]) = nw;
                __syncthreads();
                buf = nb;
            }
        }
        __syncthreads();
    }

    #pragma unroll
    for (int mi = 0; mi < 2; ++mi) {
        #pragma unroll
        for (int half = 0; half < 2; ++half) {
            int grow = i0 + wr * 32 + mi * 16 + r4 + half * 8;
            if (grow >= NN) continue;
            #pragma unroll
            for (int ni = 0; ni < 8; ++ni) {
                int gcol = j0 + wc * 64 + ni * 8 + c4 * 2;
                if (gcol >= Nout) continue;
                float v0 = acc[mi][ni][half * 2 + 0] + (bias ? bias[gcol] : 0.f);
                float v1 = acc[mi][ni][half * 2 + 1] + (bias ? bias[gcol + 1] : 0.f);
                if (RELU) { v0 = fmaxf(v0, 0.f); v1 = fmaxf(v1, 0.f); }
                if (HALF_OUT) {
                    __half2 hv = __floats2half2_rn(v0, v1);
                    *reinterpret_cast<__half2*>(Ch + (size_t)grow * Nout + gcol) = hv;
                } else {
                    *reinterpret_cast<float2*>(Cf + (size_t)grow * Nout + gcol) =
                        make_float2(v0, v1);
                }
            }
        }
    }
}

// ------- layer-2 tail: 4 nodes/warp, 8 lanes/node, gather + log_softmax ------
__global__ void agg40h_lsm_k(const float* __restrict__ b2, float* __restrict__ out) {
    int warpId = (int)((blockIdx.x * blockDim.x + threadIdx.x) >> 5);
    int lane = threadIdx.x & 31;
    int g = lane >> 3, sub = lane & 7;
    int node = warpId * 4 + g;
    bool nvalid = (node < NN);
    bool act = nvalid && (sub < 5);
    int beg = 0, end = 0;
    if (nvalid) { beg = g_rowptr[node]; end = g_rowptr[node + 1]; }

    float s[8];
    #pragma unroll
    for (int q = 0; q < 8; ++q) s[q] = 0.f;
    int e = beg;
    for (; e + 3 < end; e += 4) {
        int i0 = g_col[e], i1 = g_col[e + 1], i2 = g_col[e + 2], i3 = g_col[e + 3];
        if (act) {
            uint4 v0 = __ldg(reinterpret_cast<const uint4*>(g_zh + (size_t)i0 * 80) + sub);
            uint4 v1 = __ldg(reinterpret_cast<const uint4*>(g_zh + (size_t)i1 * 80) + sub);
            uint4 v2 = __ldg(reinterpret_cast<const uint4*>(g_zh + (size_t)i2 * 80) + sub);
            uint4 v3 = __ldg(reinterpret_cast<const uint4*>(g_zh + (size_t)i3 * 80) + sub);
            acc8(s, v0); acc8(s, v1); acc8(s, v2); acc8(s, v3);
        }
    }
    for (; e < end; ++e) {
        int i0 = g_col[e];
        if (act) {
            uint4 v0 = __ldg(reinterpret_cast<const uint4*>(g_zh + (size_t)i0 * 80) + sub);
            acc8(s, v0);
        }
    }

    float v[8];
    float mymax = -INFINITY;
    if (act) {
        float inv = g_invdeg[node];
        float rf[8];
        #pragma unroll
        for (int q = 0; q < 8; ++q) rf[q] = 0.f;
        uint4 rv = __ldg(reinterpret_cast<const uint4*>(g_zh + (size_t)node * 80 + 40) + sub);
        acc8(rf, rv);
        float4 bb0 = *reinterpret_cast<const float4*>(b2 + 8 * sub);
        float4 bb1 = *reinterpret_cast<const float4*>(b2 + 8 * sub + 4);
        float bb[8] = {bb0.x, bb0.y, bb0.z, bb0.w, bb1.x, bb1.y, bb1.z, bb1.w};
        #pragma unroll
        for (int q = 0; q < 8; ++q) {
            v[q] = s[q] * inv + rf[q] + bb[q];
            mymax = fmaxf(mymax, v[q]);
        }
    }
    // group-local (8-lane) reductions: xor 4/2/1 stays inside each group
    #pragma unroll
    for (int off = 4; off > 0; off >>= 1)
        mymax = fmaxf(mymax, __shfl_xor_sync(0xffffffffu, mymax, off));
    float se = 0.f;
    if (act) {
        #pragma unroll
        for (int q = 0; q < 8; ++q) se += expf(v[q] - mymax);
    }
    #pragma unroll
    for (int off = 4; off > 0; off >>= 1)
        se += __shfl_xor_sync(0xffffffffu, se, off);
    float ls = mymax + logf(se);
    if (act) {
        float4 o0 = make_float4(v[0] - ls, v[1] - ls, v[2] - ls, v[3] - ls);
        float4 o1 = make_float4(v[4] - ls, v[5] - ls, v[6] - ls, v[7] - ls);
        float* po = out + (size_t)node * DOUT + 8 * sub;
        *reinterpret_cast<float4*>(po) = o0;
        *reinterpret_cast<float4*>(po + 4) = o1;
    }
}

// ---------------- launch -----------------------------------------------------
extern "C" void kernel_launch(void* const* d_in, const int* in_sizes, int n_in,
                              void* d_out, int out_size) {
    const float* x   = (const float*)d_in[0];
    const int*   ei  = (const int*)d_in[1];
    const int*   src = ei;
    const int*   dst = ei + NE;
    const float* Wl0 = (const float*)d_in[2];
    const float* Wr0 = (const float*)d_in[3];
    const float* b0  = (const float*)d_in[4];
    const float* Wl1 = (const float*)d_in[5];
    const float* Wr1 = (const float*)d_in[6];
    const float* b1  = (const float*)d_in[7];
    const float* Wl2 = (const float*)d_in[8];
    const float* Wr2 = (const float*)d_in[9];
    const float* b2  = (const float*)d_in[10];
    float* out = (float*)d_out;

    __half *p_xh, *p_meanh, *p_h0h, *p_h1h, *p_zh;
    __half *p_Wl0h, *p_Wr0h, *p_Wl1h, *p_Wr1h, *p_W2h;
    cudaGetSymbolAddress((void**)&p_xh, g_xh);
    cudaGetSymbolAddress((void**)&p_meanh, g_meanh);
    cudaGetSymbolAddress((void**)&p_h0h, g_h0h);
    cudaGetSymbolAddress((void**)&p_h1h, g_h1h);
    cudaGetSymbolAddress((void**)&p_zh, g_zh);
    cudaGetSymbolAddress((void**)&p_Wl0h, g_Wl0h);
    cudaGetSymbolAddress((void**)&p_Wr0h, g_Wr0h);
    cudaGetSymbolAddress((void**)&p_Wl1h, g_Wl1h);
    cudaGetSymbolAddress((void**)&p_Wr1h, g_Wr1h);
    cudaGetSymbolAddress((void**)&p_W2h, g_W2h);

    static cudaStream_t s2 = nullptr;
    static cudaEvent_t evFork, evCSR;
    if (!s2) {
        cudaStreamCreateWithFlags(&s2, cudaStreamNonBlocking);
        cudaEventCreateWithFlags(&evFork, cudaEventDisableTiming);
        cudaEventCreateWithFlags(&evCSR, cudaEventDisableTiming);
    }

    int gemmBlocks = (NN + 127) / 128;  // 782
    dim3 gz(gemmBlocks, 1);             // Nout=80
    int aggBlocks = (NN * 32 + 255) / 256;
    int tailBlocks = (NN / 4 * 32 + 255) / 256;   // 4 nodes per warp

    // ---- fork: CSR chain on stream B || prep on capture stream --------------
    cudaEventRecord(evFork, 0);
    cudaStreamWaitEvent(s2, evFork, 0);

    zero_deg_k<<<(NN + 255) / 256, 256, 0, s2>>>();
    count_deg_k<<<(NE + 255) / 256, 256, 0, s2>>>(dst);
    scan1_k<<<NB1, 512, 0, s2>>>();
    scan2_k<<<1, 256, 0, s2>>>();
    scan3_k<<<(NN + 255) / 256, 256, 0, s2>>>();
    fill_csr_k<<<(NE + 255) / 256, 256, 0, s2>>>(src, dst);
    cudaEventRecord(evCSR, s2);

    prep_k<<<(PREP_TOTAL + 255) / 256, 256>>>(x, Wl0, Wr0, Wl1, Wr1, Wl2, Wr2);

    // ---- join ----------------------------------------------------------------
    cudaStreamWaitEvent(0, evCSR, 0);

    // layer 0
    aggregate_h_k<<<aggBlocks, 256>>>(p_xh);
    gemm_wide_k<<<gemmBlocks, 512>>>(p_meanh, p_xh, p_Wl0h, p_Wr0h, b0, p_h0h);
    // layer 1
    aggregate_h_k<<<aggBlocks, 256>>>(p_h0h);
    gemm_wide_k<<<gemmBlocks, 512>>>(p_meanh, p_h0h, p_Wl1h, p_Wr1h, b1, p_h1h);
    // layer 2: project to 80-dim fp16 first (linearity), then aggregate + softmax
    gemm_f16_k<false, true><<<gz, 256>>>(p_h1h, nullptr, p_W2h, nullptr, nullptr,
                                         p_zh, nullptr, 80, 1);
    agg40h_lsm_k<<<tailBlocks, 256>>>(b2, out);
}

// round 16
// speedup vs baseline: 1.3538x; 1.0284x over previous
#include <cuda_runtime.h>
#include <cuda_fp16.h>
#include <math.h>
#include <stdint.h>

#define NN   100000
#define NE   1600000
#define DIM  256
#define DOUT 40

// ---------------- scratch (static device globals; no runtime alloc) ----------
__device__ int    g_deg[NN];
__device__ int    g_cursor[NN];
__device__ int    g_rowptr[NN + 1];
__device__ int    g_col[NE];
__device__ int    g_bsum[256];
__device__ float  g_invdeg[NN];
__device__ __half g_xh[(size_t)NN * DIM];
__device__ __half g_meanh[(size_t)NN * DIM];
__device__ __half g_h0h[(size_t)NN * DIM];
__device__ __half g_h1h[(size_t)NN * DIM];
__device__ __half g_zh[(size_t)NN * 80];       // layer-2 projected [yl(40)|yr(40)] fp16
__device__ __half g_Wl0h[DIM * DIM];           // transposed [n][k] fp16
__device__ __half g_Wr0h[DIM * DIM];
__device__ __half g_Wl1h[DIM * DIM];
__device__ __half g_Wr1h[DIM * DIM];
__device__ __half g_W2h[80 * DIM];             // [n(80)][k(256)]

// ---------------- prep: conv_x + all weight packs ----------------------------
#define PREP_TOTAL 6682624
__global__ void prep_k(const float* __restrict__ x,
                       const float* __restrict__ Wl0, const float* __restrict__ Wr0,
                       const float* __restrict__ Wl1, const float* __restrict__ Wr1,
                       const float* __restrict__ Wl2, const float* __restrict__ Wr2) {
    int i = blockIdx.x * blockDim.x + threadIdx.x;
    if (i < 6400000) {
        float4 v = *reinterpret_cast<const float4*>(x + (size_t)i * 4);
        __half2 h0 = __floats2half2_rn(v.x, v.y);
        __half2 h1 = __floats2half2_rn(v.z, v.w);
        uint2 pk;
        pk.x = *reinterpret_cast<unsigned*>(&h0);
        pk.y = *reinterpret_cast<unsigned*>(&h1);
        *reinterpret_cast<uint2*>(g_xh + (size_t)i * 4) = pk;
    } else if (i < 6662144) {
        int j = i - 6400000;
        int w = j >> 16;
        int r = j & 65535;
        const float* W = (w == 0) ? Wl0 : (w == 1) ? Wr0 : (w == 2) ? Wl1 : Wr1;
        __half* o = (w == 0) ? g_Wl0h : (w == 1) ? g_Wr0h : (w == 2) ? g_Wl1h : g_Wr1h;
        int n = r >> 8, k = r & 255;
        o[(size_t)n * DIM + k] = __float2half_rn(W[(size_t)k * DIM + n]);
    } else if (i < PREP_TOTAL) {
        int j = i - 6662144;
        int w = j / 10240, r = j % 10240;
        const float* W = w ? Wr2 : Wl2;
        int n = r >> 8, k = r & 255;
        g_W2h[(size_t)(w * 40 + n) * DIM + k] = __float2half_rn(W[(size_t)k * DOUT + n]);
    }
}

// ---------------- CSR build --------------------------------------------------
__global__ void zero_deg_k() {
    int i = blockIdx.x * blockDim.x + threadIdx.x;
    if (i < NN) g_deg[i] = 0;
}

__global__ void count_deg_k(const int* __restrict__ dst) {
    int e = blockIdx.x * blockDim.x + threadIdx.x;
    if (e < NE) atomicAdd(&g_deg[dst[e]], 1);
}

#define NB1 196   // ceil(NN / 512)
__global__ void scan1_k() {
    __shared__ int wsum[16];
    int tid = threadIdx.x, lane = tid & 31, wid = tid >> 5;
    int i = blockIdx.x * 512 + tid;
    int v = (i < NN) ? g_deg[i] : 0;
    int x = v;
    #pragma unroll
    for (int off = 1; off < 32; off <<= 1) {
        int t = __shfl_up_sync(0xffffffffu, x, off);
        if (lane >= off) x += t;
    }
    if (lane == 31) wsum[wid] = x;
    __syncthreads();
    if (wid == 0 && lane < 16) {
        int w = wsum[lane];
        #pragma unroll
        for (int off = 1; off < 16; off <<= 1) {
            int t = __shfl_up_sync(0x0000ffffu, w, off);
            if (lane >= off) w += t;
        }
        wsum[lane] = w;
    }
    __syncthreads();
    int excl = x - v + ((wid > 0) ? wsum[wid - 1] : 0);
    if (i < NN) g_rowptr[i] = excl;
    if (tid == 0) g_bsum[blockIdx.x] = wsum[15];
}

__global__ void scan2_k() {
    __shared__ int sm[256];
    int t = threadIdx.x;
    int v = (t < NB1) ? g_bsum[t] : 0;
    sm[t] = v;
    __syncthreads();
    #pragma unroll
    for (int off = 1; off < 256; off <<= 1) {
        int add = (t >= off) ? sm[t - off] : 0;
        __syncthreads();
        sm[t] += add;
        __syncthreads();
    }
    if (t < NB1) g_bsum[t] = sm[t] - v;
    if (t == NB1 - 1) g_rowptr[NN] = sm[t];
}

__global__ void scan3_k() {
    int i = blockIdx.x * blockDim.x + threadIdx.x;
    if (i < NN) {
        int e = g_rowptr[i] + g_bsum[i >> 9];
        g_rowptr[i] = e;
        g_cursor[i] = e;
        int d = g_deg[i];
        g_invdeg[i] = 1.0f / (float)((d > 1) ? d : 1);
    }
}

__global__ void fill_csr_k(const int* __restrict__ src, const int* __restrict__ dst) {
    int e = blockIdx.x * blockDim.x + threadIdx.x;
    if (e < NE) {
        int d = dst[e];
        int p = atomicAdd(&g_cursor[d], 1);
        g_col[p] = src[e];
    }
}

// ---------------- aggregation (fp16 gather, fp32 accumulate) -----------------
__device__ __forceinline__ void acc8(float* s, uint4 v) {
    __half2 a = *reinterpret_cast<__half2*>(&v.x);
    __half2 b = *reinterpret_cast<__half2*>(&v.y);
    __half2 c = *reinterpret_cast<__half2*>(&v.z);
    __half2 d = *reinterpret_cast<__half2*>(&v.w);
    float2 fa = __half22float2(a), fb = __half22float2(b);
    float2 fc = __half22float2(c), fd = __half22float2(d);
    s[0] += fa.x; s[1] += fa.y; s[2] += fb.x; s[3] += fb.y;
    s[4] += fc.x; s[5] += fc.y; s[6] += fd.x; s[7] += fd.y;
}

__global__ void aggregate_h_k(const __half* __restrict__ h) {
    int node = (int)((blockIdx.x * blockDim.x + threadIdx.x) >> 5);
    if (node >= NN) return;
    int lane = threadIdx.x & 31;
    int beg = g_rowptr[node], end = g_rowptr[node + 1];
    float s[8];
    #pragma unroll
    for (int q = 0; q < 8; ++q) s[q] = 0.f;
    int e = beg;
    // 8-edge unroll: 8 independent gathers in flight before accumulation
    for (; e + 7 < end; e += 8) {
        int i0 = g_col[e],     i1 = g_col[e + 1], i2 = g_col[e + 2], i3 = g_col[e + 3];
        int i4 = g_col[e + 4], i5 = g_col[e + 5], i6 = g_col[e + 6], i7 = g_col[e + 7];
        uint4 v0 = __ldg(reinterpret_cast<const uint4*>(h + (size_t)i0 * DIM) + lane);
        uint4 v1 = __ldg(reinterpret_cast<const uint4*>(h + (size_t)i1 * DIM) + lane);
        uint4 v2 = __ldg(reinterpret_cast<const uint4*>(h + (size_t)i2 * DIM) + lane);
        uint4 v3 = __ldg(reinterpret_cast<const uint4*>(h + (size_t)i3 * DIM) + lane);
        uint4 v4 = __ldg(reinterpret_cast<const uint4*>(h + (size_t)i4 * DIM) + lane);
        uint4 v5 = __ldg(reinterpret_cast<const uint4*>(h + (size_t)i5 * DIM) + lane);
        uint4 v6 = __ldg(reinterpret_cast<const uint4*>(h + (size_t)i6 * DIM) + lane);
        uint4 v7 = __ldg(reinterpret_cast<const uint4*>(h + (size_t)i7 * DIM) + lane);
        acc8(s, v0); acc8(s, v1); acc8(s, v2); acc8(s, v3);
        acc8(s, v4); acc8(s, v5); acc8(s, v6); acc8(s, v7);
    }
    for (; e + 3 < end; e += 4) {
        int i0 = g_col[e], i1 = g_col[e + 1], i2 = g_col[e + 2], i3 = g_col[e + 3];
        uint4 v0 = __ldg(reinterpret_cast<const uint4*>(h + (size_t)i0 * DIM) + lane);
        uint4 v1 = __ldg(reinterpret_cast<const uint4*>(h + (size_t)i1 * DIM) + lane);
        uint4 v2 = __ldg(reinterpret_cast<const uint4*>(h + (size_t)i2 * DIM) + lane);
        uint4 v3 = __ldg(reinterpret_cast<const uint4*>(h + (size_t)i3 * DIM) + lane);
        acc8(s, v0); acc8(s, v1); acc8(s, v2); acc8(s, v3);
    }
    for (; e < end; ++e) {
        int i0 = g_col[e];
        uint4 v0 = __ldg(reinterpret_cast<const uint4*>(h + (size_t)i0 * DIM) + lane);
        acc8(s, v0);
    }
    float inv = g_invdeg[node];
    __half2 o0 = __floats2half2_rn(s[0] * inv, s[1] * inv);
    __half2 o1 = __floats2half2_rn(s[2] * inv, s[3] * inv);
    __half2 o2 = __floats2half2_rn(s[4] * inv, s[5] * inv);
    __half2 o3 = __floats2half2_rn(s[6] * inv, s[7] * inv);
    uint4 pk;
    pk.x = *reinterpret_cast<unsigned*>(&o0);
    pk.y = *reinterpret_cast<unsigned*>(&o1);
    pk.z = *reinterpret_cast<unsigned*>(&o2);
    pk.w = *reinterpret_cast<unsigned*>(&o3);
    *(reinterpret_cast<uint4*>(g_meanh + (size_t)node * DIM) + lane) = pk;
}

// ---------------- fp16 tensor-core GEMM primitives ----------------------------
__device__ __forceinline__ uint32_t smem_u32(const void* p) {
    uint32_t a;
    asm("{ .reg .u64 t; cvta.to.shared.u64 t, %1; cvt.u32.u64 %0, t; }"
        : "=r"(a) : "l"(p));
    return a;
}

__device__ __forceinline__ void mma_f16(float* d, const unsigned* a, const unsigned* b) {
    asm volatile(
        "mma.sync.aligned.m16n8k16.row.col.f32.f16.f16.f32 "
        "{%0,%1,%2,%3}, {%4,%5,%6,%7}, {%8,%9}, {%0,%1,%2,%3};"
        : "+f"(d[0]), "+f"(d[1]), "+f"(d[2]), "+f"(d[3])
        : "r"(a[0]), "r"(a[1]), "r"(a[2]), "r"(a[3]),
          "r"(b[0]), "r"(b[1]));
}

__device__ __forceinline__ void ldsm_x4(unsigned& r0, unsigned& r1,
                                        unsigned& r2, unsigned& r3, uint32_t addr) {
    asm volatile("ldmatrix.sync.aligned.m8n8.x4.shared.b16 {%0,%1,%2,%3}, [%4];"
                 : "=r"(r0), "=r"(r1), "=r"(r2), "=r"(r3) : "r"(addr));
}

#define SA 24

// ---- wide GEMM for layers 0/1: BM=128, BN=256, 512 threads (16 warps 4x4) ---
__global__ __launch_bounds__(512) void gemm_wide_k(
    const __half* __restrict__ A0, const __half* __restrict__ A1,
    const __half* __restrict__ W0, const __half* __restrict__ W1,
    const float* __restrict__ bias, __half* __restrict__ Ch)
{
    __shared__ __align__(16) __half As[2][128 * SA];
    __shared__ __align__(16) __half Ws[2][256 * SA];
    int tid = threadIdx.x;
    int lane = tid & 31, wid = tid >> 5;
    int wr = wid >> 2, wc = wid & 3;       // 4x4 warp grid
    int i0 = blockIdx.x * 128;

    const bool aload = (tid < 256);
    int arow = (tid & 255) >> 1, akb = (tid & 1) << 3;
    int gi = i0 + arow; if (gi >= NN) gi = NN - 1;
    int wrow = tid >> 1;
    int wkb = (tid & 1) << 3;

    float acc[2][8][4];
    #pragma unroll
    for (int mi = 0; mi < 2; ++mi)
        #pragma unroll
        for (int ni = 0; ni < 8; ++ni)
            #pragma unroll
            for (int q = 0; q < 4; ++q) acc[mi][ni][q] = 0.f;

    const int lrow = lane & 15;
    const int lcol = (lane >> 4) << 3;
    const uint32_t a_sm0 = smem_u32(&As[0][0]);
    const uint32_t w_sm0 = smem_u32(&Ws[0][0]);
    const uint32_t abufstride = 128 * SA * 2;
    const uint32_t wbufstride = 256 * SA * 2;
    const int r4 = lane >> 2, c4 = lane & 3;

    #pragma unroll
    for (int p = 0; p < 2; ++p) {
        const __half* Ap = p ? A1 : A0;
        const __half* Wp = p ? W1 : W0;

        {
            if (aload) {
                uint4 ra = *reinterpret_cast<const uint4*>(Ap + (size_t)gi * DIM + akb);
                *reinterpret_cast<uint4*>(&As[0][arow * SA + akb]) = ra;
            }
            uint4 rw = *reinterpret_cast<const uint4*>(Wp + (size_t)wrow * DIM + wkb);
            *reinterpret_cast<uint4*>(&Ws[0][wrow * SA + wkb]) = rw;
        }
        __syncthreads();

        int buf = 0;
        for (int k0 = 16; k0 <= DIM; k0 += 16) {
            uint4 na, nw;
            bool have_next = (k0 < DIM);
            if (have_next) {
                if (aload)
                    na = *reinterpret_cast<const uint4*>(Ap + (size_t)gi * DIM + k0 + akb);
                nw = *reinterpret_cast<const uint4*>(Wp + (size_t)wrow * DIM + k0 + wkb);
            }

            uint32_t a_sm = a_sm0 + buf * abufstride;
            uint32_t w_sm = w_sm0 + buf * wbufstride;
            unsigned afr[2][4];
            #pragma unroll
            for (int mi = 0; mi < 2; ++mi) {
                uint32_t addr = a_sm + (uint32_t)(((wr * 32 + mi * 16 + lrow) * SA + lcol) * 2);
                ldsm_x4(afr[mi][0], afr[mi][1], afr[mi][2], afr[mi][3], addr);
            }
            unsigned bfr[8][2];
            #pragma unroll
            for (int p4 = 0; p4 < 4; ++p4) {
                uint32_t addr = w_sm + (uint32_t)(((wc * 64 + p4 * 16 + lrow) * SA + lcol) * 2);
                ldsm_x4(bfr[2 * p4][0], bfr[2 * p4 + 1][0],
                        bfr[2 * p4][1], bfr[2 * p4 + 1][1], addr);
            }
            #pragma unroll
            for (int mi = 0; mi < 2; ++mi)
                #pragma unroll
                for (int ni = 0; ni < 8; ++ni)
                    mma_f16(acc[mi][ni], afr[mi], bfr[ni]);

            if (have_next) {
                int nb = buf ^ 1;
                if (aload)
                    *reinterpret_cast<uint4*>(&As[nb][arow * SA + akb]) = na;
                *reinterpret_cast<uint4*>(&Ws[nb][wrow * SA + wkb]) = nw;
                __syncthreads();
                buf = nb;
            }
        }
        __syncthreads();
    }

    #pragma unroll
    for (int mi = 0; mi < 2; ++mi) {
        #pragma unroll
        for (int half = 0; half < 2; ++half) {
            int grow = i0 + wr * 32 + mi * 16 + r4 + half * 8;
            if (grow >= NN) continue;
            #pragma unroll
            for (int ni = 0; ni < 8; ++ni) {
                int gcol = wc * 64 + ni * 8 + c4 * 2;
                float v0 = acc[mi][ni][half * 2 + 0] + bias[gcol];
                float v1 = acc[mi][ni][half * 2 + 1] + bias[gcol + 1];
                v0 = fmaxf(v0, 0.f); v1 = fmaxf(v1, 0.f);
                __half2 hv = __floats2half2_rn(v0, v1);
                *reinterpret_cast<__half2*>(Ch + (size_t)grow * 256 + gcol) = hv;
            }
        }
    }
}

// ---- 256-thread GEMM kept for the z projection (Nout=80) --------------------
template<bool RELU, bool HALF_OUT>
__global__ __launch_bounds__(256) void gemm_f16_k(
    const __half* __restrict__ A0, const __half* __restrict__ A1,
    const __half* __restrict__ W0, const __half* __restrict__ W1,
    const float* __restrict__ bias,
    __half* __restrict__ Ch, float* __restrict__ Cf,
    int Nout, int nphase)
{
    __shared__ __align__(16) __half As[2][128 * SA];
    __shared__ __align__(16) __half Ws[2][128 * SA];
    int tid = threadIdx.x;
    int lane = tid & 31, wid = tid >> 5;
    int wr = wid >> 1, wc = wid & 1;
    int i0 = blockIdx.x * 128, j0 = blockIdx.y * 128;

    int arow = tid >> 1, akb = (tid & 1) << 3;
    int gi = i0 + arow; if (gi >= NN) gi = NN - 1;
    const bool w_ok = (j0 + arow < Nout);

    float acc[2][8][4];
    #pragma unroll
    for (int mi = 0; mi < 2; ++mi)
        #pragma unroll
        for (int ni = 0; ni < 8; ++ni)
            #pragma unroll
            for (int q = 0; q < 4; ++q) acc[mi][ni][q] = 0.f;

    const int lrow = lane & 15;
    const int lcol = (lane >> 4) << 3;
    const uint32_t a_sm0 = smem_u32(&As[0][0]);
    const uint32_t w_sm0 = smem_u32(&Ws[0][0]);
    const uint32_t bufstride = 128 * SA * 2;
    const int r4 = lane >> 2, c4 = lane & 3;

    for (int p = 0; p < nphase; ++p) {
        const __half* Ap = p ? A1 : A0;
        const __half* Wp = p ? W1 : W0;

        {
            uint4 ra = *reinterpret_cast<const uint4*>(Ap + (size_t)gi * DIM + akb);
            uint4 rw = make_uint4(0, 0, 0, 0);
            if (w_ok) rw = *reinterpret_cast<const uint4*>(Wp + (size_t)(j0 + arow) * DIM + akb);
            *reinterpret_cast<uint4*>(&As[0][arow * SA + akb]) = ra;
            *reinterpret_cast<uint4*>(&Ws[0][arow * SA + akb]) = rw;
        }
        __syncthreads();

        int buf = 0;
        for (int k0 = 16; k0 <= DIM; k0 += 16) {
            uint4 na, nw;
            bool have_next = (k0 < DIM);
            if (have_next) {
                na = *reinterpret_cast<const uint4*>(Ap + (size_t)gi * DIM + k0 + akb);
                nw = make_uint4(0, 0, 0, 0);
                if (w_ok) nw = *reinterpret_cast<const uint4*>(Wp + (size_t)(j0 + arow) * DIM + k0 + akb);
            }

            uint32_t a_sm = a_sm0 + buf * bufstride;
            uint32_t w_sm = w_sm0 + buf * bufstride;
            unsigned afr[2][4];
            #pragma unroll
            for (int mi = 0; mi < 2; ++mi) {
                uint32_t addr = a_sm + (uint32_t)(((wr * 32 + mi * 16 + lrow) * SA + lcol) * 2);
                ldsm_x4(afr[mi][0], afr[mi][1], afr[mi][2], afr[mi][3], addr);
            }
            unsigned bfr[8][2];
            #pragma unroll
            for (int p4 = 0; p4 < 4; ++p4) {
                uint32_t addr = w_sm + (uint32_t)(((wc * 64 + p4 * 16 + lrow) * SA + lcol) * 2);
                ldsm_x4(bfr[2 * p4][0], bfr[2 * p4 + 1][0],
                        bfr[2 * p4][1], bfr[2 * p4 + 1][1], addr);
            }
            #pragma unroll
            for (int mi = 0; mi < 2; ++mi)
                #pragma unroll
                for (int ni = 0; ni < 8; ++ni)
                    mma_f16(acc[mi][ni], afr[mi], bfr[ni]);

            if (have_next) {
                int nb = buf ^ 1;
                *reinterpret_cast<uint4*>(&As[nb][arow * SA + akb]) = na;
                *reinterpret_cast<uint4*>(&Ws[nb][arow * SA + akb]) = nw;
                __syncthreads();
                buf = nb;
            }
        }
        __syncthreads();
    }

    #pragma unroll
    for (int mi = 0; mi < 2; ++mi) {
        #pragma unroll
        for (int half = 0; half < 2; ++half) {
            int grow = i0 + wr * 32 + mi * 16 + r4 + half * 8;
            if (grow >= NN) continue;
            #pragma unroll
            for (int ni = 0; ni < 8; ++ni) {
                int gcol = j0 + wc * 64 + ni * 8 + c4 * 2;
                if (gcol >= Nout) continue;
                float v0 = acc[mi][ni][half * 2 + 0] + (bias ? bias[gcol] : 0.f);
                float v1 = acc[mi][ni][half * 2 + 1] + (bias ? bias[gcol + 1] : 0.f);
                if (RELU) { v0 = fmaxf(v0, 0.f); v1 = fmaxf(v1, 0.f); }
                if (HALF_OUT) {
                    __half2 hv = __floats2half2_rn(v0, v1);
                    *reinterpret_cast<__half2*>(Ch + (size_t)grow * Nout + gcol) = hv;
                } else {
                    *reinterpret_cast<float2*>(Cf + (size_t)grow * Nout + gcol) =
                        make_float2(v0, v1);
                }
            }
        }
    }
}

// ------- layer-2 tail: 4 nodes/warp, 8 lanes/node, gather + log_softmax ------
__global__ void agg40h_lsm_k(const float* __restrict__ b2, float* __restrict__ out) {
    int warpId = (int)((blockIdx.x * blockDim.x + threadIdx.x) >> 5);
    int lane = threadIdx.x & 31;
    int g = lane >> 3, sub = lane & 7;
    int node = warpId * 4 + g;
    bool nvalid = (node < NN);
    bool act = nvalid && (sub < 5);
    int beg = 0, end = 0;
    if (nvalid) { beg = g_rowptr[node]; end = g_rowptr[node + 1]; }

    float s[8];
    #pragma unroll
    for (int q = 0; q < 8; ++q) s[q] = 0.f;
    int e = beg;
    for (; e + 3 < end; e += 4) {
        int i0 = g_col[e], i1 = g_col[e + 1], i2 = g_col[e + 2], i3 = g_col[e + 3];
        if (act) {
            uint4 v0 = __ldg(reinterpret_cast<const uint4*>(g_zh + (size_t)i0 * 80) + sub);
            uint4 v1 = __ldg(reinterpret_cast<const uint4*>(g_zh + (size_t)i1 * 80) + sub);
            uint4 v2 = __ldg(reinterpret_cast<const uint4*>(g_zh + (size_t)i2 * 80) + sub);
            uint4 v3 = __ldg(reinterpret_cast<const uint4*>(g_zh + (size_t)i3 * 80) + sub);
            acc8(s, v0); acc8(s, v1); acc8(s, v2); acc8(s, v3);
        }
    }
    for (; e < end; ++e) {
        int i0 = g_col[e];
        if (act) {
            uint4 v0 = __ldg(reinterpret_cast<const uint4*>(g_zh + (size_t)i0 * 80) + sub);
            acc8(s, v0);
        }
    }

    float v[8];
    float mymax = -INFINITY;
    if (act) {
        float inv = g_invdeg[node];
        float rf[8];
        #pragma unroll
        for (int q = 0; q < 8; ++q) rf[q] = 0.f;
        uint4 rv = __ldg(reinterpret_cast<const uint4*>(g_zh + (size_t)node * 80 + 40) + sub);
        acc8(rf, rv);
        float4 bb0 = *reinterpret_cast<const float4*>(b2 + 8 * sub);
        float4 bb1 = *reinterpret_cast<const float4*>(b2 + 8 * sub + 4);
        float bb[8] = {bb0.x, bb0.y, bb0.z, bb0.w, bb1.x, bb1.y, bb1.z, bb1.w};
        #pragma unroll
        for (int q = 0; q < 8; ++q) {
            v[q] = s[q] * inv + rf[q] + bb[q];
            mymax = fmaxf(mymax, v[q]);
        }
    }
    // group-local (8-lane) reductions: xor 4/2/1 stays inside each group
    #pragma unroll
    for (int off = 4; off > 0; off >>= 1)
        mymax = fmaxf(mymax, __shfl_xor_sync(0xffffffffu, mymax, off));
    float se = 0.f;
    if (act) {
        #pragma unroll
        for (int q = 0; q < 8; ++q) se += expf(v[q] - mymax);
    }
    #pragma unroll
    for (int off = 4; off > 0; off >>= 1)
        se += __shfl_xor_sync(0xffffffffu, se, off);
    float ls = mymax + logf(se);
    if (act) {
        float4 o0 = make_float4(v[0] - ls, v[1] - ls, v[2] - ls, v[3] - ls);
        float4 o1 = make_float4(v[4] - ls, v[5] - ls, v[6] - ls, v[7] - ls);
        float* po = out + (size_t)node * DOUT + 8 * sub;
        *reinterpret_cast<float4*>(po) = o0;
        *reinterpret_cast<float4*>(po + 4) = o1;
    }
}

// ---------------- launch -----------------------------------------------------
extern "C" void kernel_launch(void* const* d_in, const int* in_sizes, int n_in,
                              void* d_out, int out_size) {
    const float* x   = (const float*)d_in[0];
    const int*   ei  = (const int*)d_in[1];
    const int*   src = ei;
    const int*   dst = ei + NE;
    const float* Wl0 = (const float*)d_in[2];
    const float* Wr0 = (const float*)d_in[3];
    const float* b0  = (const float*)d_in[4];
    const float* Wl1 = (const float*)d_in[5];
    const float* Wr1 = (const float*)d_in[6];
    const float* b1  = (const float*)d_in[7];
    const float* Wl2 = (const float*)d_in[8];
    const float* Wr2 = (const float*)d_in[9];
    const float* b2  = (const float*)d_in[10];
    float* out = (float*)d_out;

    __half *p_xh, *p_meanh, *p_h0h, *p_h1h, *p_zh;
    __half *p_Wl0h, *p_Wr0h, *p_Wl1h, *p_Wr1h, *p_W2h;
    cudaGetSymbolAddress((void**)&p_xh, g_xh);
    cudaGetSymbolAddress((void**)&p_meanh, g_meanh);
    cudaGetSymbolAddress((void**)&p_h0h, g_h0h);
    cudaGetSymbolAddress((void**)&p_h1h, g_h1h);
    cudaGetSymbolAddress((void**)&p_zh, g_zh);
    cudaGetSymbolAddress((void**)&p_Wl0h, g_Wl0h);
    cudaGetSymbolAddress((void**)&p_Wr0h, g_Wr0h);
    cudaGetSymbolAddress((void**)&p_Wl1h, g_Wl1h);
    cudaGetSymbolAddress((void**)&p_Wr1h, g_Wr1h);
    cudaGetSymbolAddress((void**)&p_W2h, g_W2h);

    static cudaStream_t s2 = nullptr;
    static cudaEvent_t evFork, evCSR;
    if (!s2) {
        cudaStreamCreateWithFlags(&s2, cudaStreamNonBlocking);
        cudaEventCreateWithFlags(&evFork, cudaEventDisableTiming);
        cudaEventCreateWithFlags(&evCSR, cudaEventDisableTiming);
    }

    int gemmBlocks = (NN + 127) / 128;  // 782
    dim3 gz(gemmBlocks, 1);             // Nout=80
    int aggBlocks = (NN * 32 + 255) / 256;
    int tailBlocks = (NN / 4 * 32 + 255) / 256;   // 4 nodes per warp

    // ---- fork: CSR chain on stream B || prep on capture stream --------------
    cudaEventRecord(evFork, 0);
    cudaStreamWaitEvent(s2, evFork, 0);

    zero_deg_k<<<(NN + 255) / 256, 256, 0, s2>>>();
    count_deg_k<<<(NE + 255) / 256, 256, 0, s2>>>(dst);
    scan1_k<<<NB1, 512, 0, s2>>>();
    scan2_k<<<1, 256, 0, s2>>>();
    scan3_k<<<(NN + 255) / 256, 256, 0, s2>>>();
    fill_csr_k<<<(NE + 255) / 256, 256, 0, s2>>>(src, dst);
    cudaEventRecord(evCSR, s2);

    prep_k<<<(PREP_TOTAL + 255) / 256, 256>>>(x, Wl0, Wr0, Wl1, Wr1, Wl2, Wr2);

    // ---- join ----------------------------------------------------------------
    cudaStreamWaitEvent(0, evCSR, 0);

    // layer 0
    aggregate_h_k<<<aggBlocks, 256>>>(p_xh);
    gemm_wide_k<<<gemmBlocks, 512>>>(p_meanh, p_xh, p_Wl0h, p_Wr0h, b0, p_h0h);
    // layer 1
    aggregate_h_k<<<aggBlocks, 256>>>(p_h0h);
    gemm_wide_k<<<gemmBlocks, 512>>>(p_meanh, p_h0h, p_Wl1h, p_Wr1h, b1, p_h1h);
    // layer 2: project to 80-dim fp16 first (linearity), then aggregate + softmax
    gemm_f16_k<false, true><<<gz, 256>>>(p_h1h, nullptr, p_W2h, nullptr, nullptr,
                                         p_zh, nullptr, 80, 1);
    agg40h_lsm_k<<<tailBlocks, 256>>>(b2, out);
}